// round 10
// baseline (speedup 1.0000x reference)
#include <cuda_runtime.h>
#include <math.h>

// Problem dimensions (fixed by the dataset)
#define NN    32768      // total nodes B*NPG
#define BBg   8          // graphs
#define NPGc  4096       // nodes per graph
#define DINc  128
#define HHc   4
#define EEc   262144
#define CDIM  512        // H*DIN
#define BHc   32         // B*H

// ---------------- tf32 helpers ----------------
__device__ __forceinline__ float tf32r(float x) {
    unsigned r;
    asm("cvt.rna.tf32.f32 %0, %1;" : "=r"(r) : "f"(x));
    return __uint_as_float(r);
}
__device__ __forceinline__ void mma8(float* c, const unsigned* a, const unsigned* b) {
    asm volatile(
        "mma.sync.aligned.m16n8k8.row.col.f32.tf32.tf32.f32 "
        "{%0,%1,%2,%3},{%4,%5,%6,%7},{%8,%9},{%0,%1,%2,%3};\n"
        : "+f"(c[0]), "+f"(c[1]), "+f"(c[2]), "+f"(c[3])
        : "r"(a[0]), "r"(a[1]), "r"(a[2]), "r"(a[3]), "r"(b[0]), "r"(b[1]));
}
__device__ __forceinline__ unsigned fbits(float x) { return __float_as_uint(x); }

// ---------------- scratch (device globals: allocation-free) ----------------
__device__ float g_q   [NN*CDIM];
__device__ float g_k   [NN*CDIM];
__device__ float g_cur [NN*CDIM];   // buffer A (holds init)
__device__ float g_cur2[NN*CDIM];   // buffer B (double buffer)
__device__ float g_acc [NN*CDIM];
__device__ float g_kvp [8*BHc*DINc*DINc]; // per-split partials
__device__ float g_kv  [BHc*DINc*DINc];
__device__ float g_vsum[BHc*DINc];
__device__ float g_ksum[BHc*DINc];
__device__ float g_den [NN*HHc];
__device__ int   g_deg   [NN];
__device__ float g_dis   [NN];
__device__ int   g_cursor[NN];
__device__ int   g_rowptr[NN];
__device__ int   g_incl  [NN];
__device__ int   g_bsum[128];
__device__ int   g_boff[128];
__device__ int   g_ecol[EEc];
__device__ float g_ew  [EEc];

// ---------------- init: cur = acc = broadcast(x over heads) ----------------
__global__ void k_init(const float* __restrict__ x) {
    int i = blockIdx.x * blockDim.x + threadIdx.x;     // float4 index over NN*CDIM/4
    int n  = i >> 7;            // 128 float4 per node
    int r  = i & 127;
    int d4 = r & 31;            // float4 within the 128-dim feature (head-replicated)
    float4 v = reinterpret_cast<const float4*>(x)[n * 32 + d4];
    reinterpret_cast<float4*>(g_cur)[i] = v;
    reinterpret_cast<float4*>(g_acc)[i] = v;
}

__global__ void k_zero_pre() {
    int i = blockIdx.x * blockDim.x + threadIdx.x;
    if (i < NN) { g_deg[i] = 0; g_cursor[i] = 0; }
    if (i < BHc * DINc) g_ksum[i] = 0.f;
}

__global__ void k_count(const int* __restrict__ row) {
    int e = blockIdx.x * blockDim.x + threadIdx.x;
    if (e < EEc) atomicAdd(&g_deg[row[e]], 1);
}

__global__ void k_dis() {
    int n = blockIdx.x * blockDim.x + threadIdx.x;
    if (n < NN) {
        int d = g_deg[n];
        g_dis[n] = (d > 0) ? (1.0f / sqrtf((float)d)) : 0.0f;
    }
}

// ---------------- prefix scan over deg -> rowptr (exclusive) ----------------
__global__ void k_scanA() {
    __shared__ int s[256];
    int t = threadIdx.x;
    int i = blockIdx.x * 256 + t;
    int v = g_deg[i];
    s[t] = v; __syncthreads();
    for (int off = 1; off < 256; off <<= 1) {
        int u = (t >= off) ? s[t - off] : 0;
        __syncthreads();
        s[t] += u;
        __syncthreads();
    }
    g_incl[i] = s[t];
    if (t == 255) g_bsum[blockIdx.x] = s[255];
}

__global__ void k_scanB() {
    __shared__ int s[128];
    int t = threadIdx.x;
    int v = g_bsum[t];
    s[t] = v; __syncthreads();
    for (int off = 1; off < 128; off <<= 1) {
        int u = (t >= off) ? s[t - off] : 0;
        __syncthreads();
        s[t] += u;
        __syncthreads();
    }
    g_boff[t] = s[t] - v;     // exclusive block offset
}

__global__ void k_scanC() {
    int i = blockIdx.x * blockDim.x + threadIdx.x;
    if (i < NN) g_rowptr[i] = g_incl[i] - g_deg[i] + g_boff[i >> 8];
}

__global__ void k_fill(const int* __restrict__ row, const int* __restrict__ col) {
    int e = blockIdx.x * blockDim.x + threadIdx.x;
    if (e < EEc) {
        int r = row[e], c = col[e];
        int pos = g_rowptr[r] + atomicAdd(&g_cursor[r], 1);
        g_ecol[pos] = c;
        g_ew[pos]   = g_dis[r] * g_dis[c];
    }
}

// ---------------- tf32 MMA GEMM: C[M,N] = scale*(A[M,K]@B[N,K]^T + bias[N]) ----------
// 128x128 block tile, 8 warps (2m x 4n), warp tile 64x32, K-chunk 32.
__global__ void __launch_bounds__(256)
k_gemm(const float* __restrict__ A, const float* __restrict__ B,
       const float* __restrict__ bias, float* __restrict__ C,
       int M, int N, int K, float scale) {
    __shared__ __align__(16) float sA[128 * 36];
    __shared__ __align__(16) float sB[128 * 36];
    int t  = threadIdx.x;
    int bm = blockIdx.y * 128;
    int bn = blockIdx.x * 128;
    int wid = t >> 5, lane = t & 31, gid = lane >> 2, tig = lane & 3;
    int wm = (wid & 1) * 64, wn = (wid >> 1) * 32;

    float c[4][4][4];
    #pragma unroll
    for (int i = 0; i < 4; i++)
        #pragma unroll
        for (int j = 0; j < 4; j++)
            #pragma unroll
            for (int r = 0; r < 4; r++) c[i][j][r] = 0.f;

    for (int kc = 0; kc < K; kc += 32) {
        #pragma unroll
        for (int l = 0; l < 4; l++) {
            int id = t + 256 * l;
            int row = id >> 3;
            int c4  = (id & 7) * 4;
            float4 v = *reinterpret_cast<const float4*>(&A[(bm + row) * K + kc + c4]);
            sA[row * 36 + c4 + 0] = tf32r(v.x);
            sA[row * 36 + c4 + 1] = tf32r(v.y);
            sA[row * 36 + c4 + 2] = tf32r(v.z);
            sA[row * 36 + c4 + 3] = tf32r(v.w);
            float4 w = *reinterpret_cast<const float4*>(&B[(bn + row) * K + kc + c4]);
            sB[row * 36 + c4 + 0] = tf32r(w.x);
            sB[row * 36 + c4 + 1] = tf32r(w.y);
            sB[row * 36 + c4 + 2] = tf32r(w.z);
            sB[row * 36 + c4 + 3] = tf32r(w.w);
        }
        __syncthreads();
        #pragma unroll
        for (int ks = 0; ks < 4; ks++) {
            int k0 = ks * 8;
            unsigned a[4][4], b[4][2];
            #pragma unroll
            for (int mt = 0; mt < 4; mt++) {
                int m = wm + 16 * mt + gid;
                a[mt][0] = fbits(sA[m * 36 + k0 + tig]);
                a[mt][1] = fbits(sA[(m + 8) * 36 + k0 + tig]);
                a[mt][2] = fbits(sA[m * 36 + k0 + tig + 4]);
                a[mt][3] = fbits(sA[(m + 8) * 36 + k0 + tig + 4]);
            }
            #pragma unroll
            for (int nt = 0; nt < 4; nt++) {
                int n = wn + 8 * nt + gid;
                b[nt][0] = fbits(sB[n * 36 + k0 + tig]);
                b[nt][1] = fbits(sB[n * 36 + k0 + tig + 4]);
            }
            #pragma unroll
            for (int mt = 0; mt < 4; mt++)
                #pragma unroll
                for (int nt = 0; nt < 4; nt++) mma8(c[mt][nt], a[mt], b[nt]);
        }
        __syncthreads();
    }

    #pragma unroll
    for (int mt = 0; mt < 4; mt++) {
        int r0 = bm + wm + 16 * mt + gid;
        #pragma unroll
        for (int nt = 0; nt < 4; nt++) {
            int col = bn + wn + 8 * nt + 2 * tig;
            float2 bb = *reinterpret_cast<const float2*>(&bias[col]);
            float2 o0, o1;
            o0.x = scale * (c[mt][nt][0] + bb.x);
            o0.y = scale * (c[mt][nt][1] + bb.y);
            o1.x = scale * (c[mt][nt][2] + bb.x);
            o1.y = scale * (c[mt][nt][3] + bb.y);
            *reinterpret_cast<float2*>(&C[r0 * N + col])       = o0;
            *reinterpret_cast<float2*>(&C[(r0 + 8) * N + col]) = o1;
        }
    }
}

// ---------------- L2-normalize rows of 128 (one warp per (n,h)) ----------------
__global__ void k_norm(float* __restrict__ buf) {
    int gt   = blockIdx.x * blockDim.x + threadIdx.x;
    int w    = gt >> 5;                 // warp over NN*HH rows
    int lane = threadIdx.x & 31;
    float4 v = reinterpret_cast<float4*>(buf)[w * 32 + lane];
    float ss = v.x * v.x + v.y * v.y + v.z * v.z + v.w * v.w;
    #pragma unroll
    for (int off = 16; off > 0; off >>= 1) ss += __shfl_xor_sync(0xffffffffu, ss, off);
    float r = 1.0f / sqrtf(ss);
    v.x *= r; v.y *= r; v.z *= r; v.w *= r;
    reinterpret_cast<float4*>(buf)[w * 32 + lane] = v;
}

// ---------------- ksum (once): column sums of normalized k per (b,h) ----------------
__global__ void k_colsum() {
    int bh = blockIdx.x;
    int b = bh >> 2, h = bh & 3;
    int nb = blockIdx.y * 128;
    int e = threadIdx.x;
    float s = 0.f;
    for (int n = 0; n < 128; n++)
        s += g_k[((b * NPGc + nb + n) * HHc + h) * DINc + e];
    atomicAdd(&g_ksum[bh * DINc + e], s);
}

// ---------------- den[n,h] = q . ksum + n_nodes (iteration-invariant) ----------------
__global__ void k_den(const int* __restrict__ n_nodes) {
    int gt   = blockIdx.x * blockDim.x + threadIdx.x;
    int w    = gt >> 5;                 // (n,h) index
    int lane = threadIdx.x & 31;
    int n = w >> 2, h = w & 3;
    int b = n >> 12;                    // NPG = 4096
    float4 q = reinterpret_cast<float4*>(g_q)[w * 32 + lane];
    float4 s = reinterpret_cast<float4*>(g_ksum)[((b << 2) | h) * 32 + lane];
    float d = q.x * s.x + q.y * s.y + q.z * s.z + q.w * s.w;
    #pragma unroll
    for (int off = 16; off > 0; off >>= 1) d += __shfl_xor_sync(0xffffffffu, d, off);
    if (lane == 0) g_den[w] = d + (float)n_nodes[b];
}

__global__ void k_zero_vsum() {
    int i = blockIdx.x * blockDim.x + threadIdx.x;
    if (i < BHc * DINc) g_vsum[i] = 0.f;
}

// ---------------- kv partials + fused vsum -------------------------------------
// Natural-layout smem [node][dim] (pad 136); transpose happens in fragment
// addressing: banks 8*tig+gid are conflict-free for both operands.
__global__ void __launch_bounds__(256) k_kv(const float* __restrict__ curOld) {
    __shared__ __align__(16) float sK[32 * 136];
    __shared__ __align__(16) float sV[32 * 136];
    int bh = blockIdx.x, sp = blockIdx.y;
    int b = bh >> 2, h = bh & 3;
    int t = threadIdx.x;
    int wid = t >> 5, lane = t & 31, gid = lane >> 2, tig = lane & 3;
    int wm = (wid & 1) * 64, wn = (wid >> 1) * 32;
    int d4 = t & 31;                 // this thread's fixed 4-dim group

    float c[4][4][4];
    #pragma unroll
    for (int i = 0; i < 4; i++)
        #pragma unroll
        for (int j = 0; j < 4; j++)
            #pragma unroll
            for (int r = 0; r < 4; r++) c[i][j][r] = 0.f;
    float vs0 = 0.f, vs1 = 0.f, vs2 = 0.f, vs3 = 0.f;  // vsum partials (raw fp32)

    int nend = sp * 512 + 512;
    for (int nb = sp * 512; nb < nend; nb += 32) {
        #pragma unroll
        for (int l = 0; l < 4; l++) {
            int id = t + 256 * l;
            int nl = id >> 5;                    // node within chunk
            int fidx = ((b * NPGc + nb + nl) * HHc + h) * DINc + 4 * d4;
            float4 vk = *reinterpret_cast<const float4*>(&g_k[fidx]);
            float4 vv = *reinterpret_cast<const float4*>(&curOld[fidx]);
            sK[nl * 136 + 4 * d4 + 0] = tf32r(vk.x);
            sK[nl * 136 + 4 * d4 + 1] = tf32r(vk.y);
            sK[nl * 136 + 4 * d4 + 2] = tf32r(vk.z);
            sK[nl * 136 + 4 * d4 + 3] = tf32r(vk.w);
            sV[nl * 136 + 4 * d4 + 0] = tf32r(vv.x);
            sV[nl * 136 + 4 * d4 + 1] = tf32r(vv.y);
            sV[nl * 136 + 4 * d4 + 2] = tf32r(vv.z);
            sV[nl * 136 + 4 * d4 + 3] = tf32r(vv.w);
            vs0 += vv.x; vs1 += vv.y; vs2 += vv.z; vs3 += vv.w;
        }
        __syncthreads();
        #pragma unroll
        for (int ks = 0; ks < 4; ks++) {
            int k0 = ks * 8;
            unsigned a[4][4], bf[4][2];
            #pragma unroll
            for (int mt = 0; mt < 4; mt++) {
                int m = wm + 16 * mt + gid;
                a[mt][0] = fbits(sK[(k0 + tig) * 136 + m]);
                a[mt][1] = fbits(sK[(k0 + tig) * 136 + m + 8]);
                a[mt][2] = fbits(sK[(k0 + tig + 4) * 136 + m]);
                a[mt][3] = fbits(sK[(k0 + tig + 4) * 136 + m + 8]);
            }
            #pragma unroll
            for (int nt = 0; nt < 4; nt++) {
                int e = wn + 8 * nt + gid;
                bf[nt][0] = fbits(sV[(k0 + tig) * 136 + e]);
                bf[nt][1] = fbits(sV[(k0 + tig + 4) * 136 + e]);
            }
            #pragma unroll
            for (int mt = 0; mt < 4; mt++)
                #pragma unroll
                for (int nt = 0; nt < 4; nt++) mma8(c[mt][nt], a[mt], bf[nt]);
        }
        __syncthreads();
    }

    // vsum partials -> global (REDG)
    atomicAdd(&g_vsum[bh * DINc + 4 * d4 + 0], vs0);
    atomicAdd(&g_vsum[bh * DINc + 4 * d4 + 1], vs1);
    atomicAdd(&g_vsum[bh * DINc + 4 * d4 + 2], vs2);
    atomicAdd(&g_vsum[bh * DINc + 4 * d4 + 3], vs3);

    float* dst = &g_kvp[(sp * BHc + bh) * (DINc * DINc)];
    #pragma unroll
    for (int mt = 0; mt < 4; mt++) {
        int r0 = wm + 16 * mt + gid;
        #pragma unroll
        for (int nt = 0; nt < 4; nt++) {
            int col = wn + 8 * nt + 2 * tig;
            *reinterpret_cast<float2*>(&dst[r0 * 128 + col]) =
                make_float2(c[mt][nt][0], c[mt][nt][1]);
            *reinterpret_cast<float2*>(&dst[(r0 + 8) * 128 + col]) =
                make_float2(c[mt][nt][2], c[mt][nt][3]);
        }
    }
}

__global__ void k_kvreduce() {
    int i = blockIdx.x * 256 + threadIdx.x;   // < 32*128*128 = 524288
    float s = 0.f;
    #pragma unroll
    for (int sp = 0; sp < 8; sp++) s += g_kvp[sp * (BHc * DINc * DINc) + i];
    g_kv[i] = s;
}

// ---------------- combine (fused GCN gather + attention + update) ---------------
// attn = (q@kv + vsum)/den; gcn gathered from curOld; curNew = .5*(gcn+attn);
// acc += curNew. Block tile: 128 nodes x 128 e, d in chunks of 32, tf32 MMA.
__global__ void __launch_bounds__(256) k_combine(const float* __restrict__ curOld,
                                                 float* __restrict__ curNew) {
    __shared__ __align__(16) float smemF[9216];    // 36 KB, aliased phases
    float* sQ  = smemF;            // [node][36]   (MMA phase)
    float* sKV = smemF + 4608;     // [d][136]     (MMA phase)
    int bh = blockIdx.x, ch = blockIdx.y;
    int b = bh >> 2, h = bh & 3;
    int t = threadIdx.x;
    int wid = t >> 5, lane = t & 31, gid = lane >> 2, tig = lane & 3;
    int wm = (wid & 1) * 64, wn = (wid >> 1) * 32;
    int nbase = ch * 128;

    float c[4][4][4];
    #pragma unroll
    for (int i = 0; i < 4; i++)
        #pragma unroll
        for (int j = 0; j < 4; j++)
            #pragma unroll
            for (int r = 0; r < 4; r++) c[i][j][r] = 0.f;

    for (int kc = 0; kc < 128; kc += 32) {
        #pragma unroll
        for (int l = 0; l < 4; l++) {
            int id = t + 256 * l;
            int row = id >> 3;
            int c4  = (id & 7) * 4;
            float4 v = *reinterpret_cast<const float4*>(
                &g_q[((b * NPGc + nbase + row) * HHc + h) * DINc + kc + c4]);
            sQ[row * 36 + c4 + 0] = tf32r(v.x);
            sQ[row * 36 + c4 + 1] = tf32r(v.y);
            sQ[row * 36 + c4 + 2] = tf32r(v.z);
            sQ[row * 36 + c4 + 3] = tf32r(v.w);
            int drow = id >> 5;          // 0..31
            int e4   = (id & 31) * 4;
            float4 w = *reinterpret_cast<const float4*>(
                &g_kv[bh * (DINc * DINc) + (kc + drow) * 128 + e4]);
            sKV[drow * 136 + e4 + 0] = tf32r(w.x);
            sKV[drow * 136 + e4 + 1] = tf32r(w.y);
            sKV[drow * 136 + e4 + 2] = tf32r(w.z);
            sKV[drow * 136 + e4 + 3] = tf32r(w.w);
        }
        __syncthreads();
        #pragma unroll
        for (int ks = 0; ks < 4; ks++) {
            int k0 = ks * 8;
            unsigned a[4][4], bfr[4][2];
            #pragma unroll
            for (int mt = 0; mt < 4; mt++) {
                int m = wm + 16 * mt + gid;
                a[mt][0] = fbits(sQ[m * 36 + k0 + tig]);
                a[mt][1] = fbits(sQ[(m + 8) * 36 + k0 + tig]);
                a[mt][2] = fbits(sQ[m * 36 + k0 + tig + 4]);
                a[mt][3] = fbits(sQ[(m + 8) * 36 + k0 + tig + 4]);
            }
            #pragma unroll
            for (int nt = 0; nt < 4; nt++) {
                int e = wn + 8 * nt + gid;
                bfr[nt][0] = fbits(sKV[(k0 + tig) * 136 + e]);
                bfr[nt][1] = fbits(sKV[(k0 + tig + 4) * 136 + e]);
            }
            #pragma unroll
            for (int mt = 0; mt < 4; mt++)
                #pragma unroll
                for (int nt = 0; nt < 4; nt++) mma8(c[mt][nt], a[mt], bfr[nt]);
        }
        __syncthreads();
    }

    // ---- fused GCN gather + merge, two 64-wide e-halves ----
    float* gcnS = smemF;           // [node][68], 128*68 floats = 34.8 KB
    int grp = t >> 4, lane16 = t & 15;
    int myhalf = wn >> 6;          // warps wn<64 merge half 0, else half 1

    #pragma unroll
    for (int ehalf = 0; ehalf < 2; ehalf++) {
        int eoff = ehalf * 64;
        // gather: 16 groups x 16 lanes; group handles nodes grp, grp+16, ...
        for (int r = 0; r < 8; r++) {
            int m  = r * 16 + grp;
            int gn = b * NPGc + nbase + m;
            int s  = g_rowptr[gn];
            int dg = g_deg[gn];
            float4 a0 = make_float4(0.f, 0.f, 0.f, 0.f);
            float4 a1 = make_float4(0.f, 0.f, 0.f, 0.f);
            int i = 0;
            for (; i + 2 <= dg; i += 2) {            // edge-pair pipelining (MLP 2)
                int   c0 = g_ecol[s + i],  c1 = g_ecol[s + i + 1];
                float w0 = g_ew[s + i],    w1 = g_ew[s + i + 1];
                float4 v0 = *reinterpret_cast<const float4*>(
                    &curOld[(c0 * HHc + h) * DINc + eoff + 4 * lane16]);
                float4 v1 = *reinterpret_cast<const float4*>(
                    &curOld[(c1 * HHc + h) * DINc + eoff + 4 * lane16]);
                a0.x += w0 * v0.x; a0.y += w0 * v0.y; a0.z += w0 * v0.z; a0.w += w0 * v0.w;
                a1.x += w1 * v1.x; a1.y += w1 * v1.y; a1.z += w1 * v1.z; a1.w += w1 * v1.w;
            }
            if (i < dg) {
                int   c0 = g_ecol[s + i];
                float w0 = g_ew[s + i];
                float4 v0 = *reinterpret_cast<const float4*>(
                    &curOld[(c0 * HHc + h) * DINc + eoff + 4 * lane16]);
                a0.x += w0 * v0.x; a0.y += w0 * v0.y; a0.z += w0 * v0.z; a0.w += w0 * v0.w;
            }
            float4 g4;
            g4.x = a0.x + a1.x; g4.y = a0.y + a1.y;
            g4.z = a0.z + a1.z; g4.w = a0.w + a1.w;
            *reinterpret_cast<float4*>(&gcnS[m * 68 + 4 * lane16]) = g4;
        }
        __syncthreads();
        // merge: only warps whose e-range is in this half
        if (myhalf == ehalf) {
            #pragma unroll
            for (int mt = 0; mt < 4; mt++) {
                #pragma unroll
                for (int rr = 0; rr < 2; rr++) {
                    int m  = wm + 16 * mt + gid + 8 * rr;
                    int gn = b * NPGc + nbase + m;
                    float inv = 1.0f / g_den[gn * HHc + h];
                    #pragma unroll
                    for (int nt = 0; nt < 4; nt++) {
                        int e    = wn + 8 * nt + 2 * tig;
                        int base = (gn * HHc + h) * DINc + e;
                        float2 vs = *reinterpret_cast<const float2*>(&g_vsum[bh * DINc + e]);
                        float2 gc = *reinterpret_cast<const float2*>(&gcnS[m * 68 + e - eoff]);
                        float2 ac = *reinterpret_cast<const float2*>(&g_acc[base]);
                        float o0 = 0.5f * (gc.x + (c[mt][nt][rr * 2 + 0] + vs.x) * inv);
                        float o1 = 0.5f * (gc.y + (c[mt][nt][rr * 2 + 1] + vs.y) * inv);
                        *reinterpret_cast<float2*>(&curNew[base]) = make_float2(o0, o1);
                        *reinterpret_cast<float2*>(&g_acc[base]) = make_float2(ac.x + o0, ac.y + o1);
                    }
                }
            }
        }
        __syncthreads();
    }
}

// ---------------- launcher ----------------
extern "C" void kernel_launch(void* const* d_in, const int* in_sizes, int n_in,
                              void* d_out, int out_size) {
    const float* x    = (const float*)d_in[0];
    const float* Wq_w = (const float*)d_in[1];
    const float* Wq_b = (const float*)d_in[2];
    const float* Wk_w = (const float*)d_in[3];
    const float* Wk_b = (const float*)d_in[4];
    const float* Wo_w = (const float*)d_in[5];
    const float* Wo_b = (const float*)d_in[6];
    const int*   edge = (const int*)d_in[7];
    const int*   nnod = (const int*)d_in[8];
    const int* row = edge;
    const int* col = edge + EEc;
    float* out = (float*)d_out;

    float *pq, *pk, *pacc, *pcurA, *pcurB;
    cudaGetSymbolAddress((void**)&pq,    g_q);
    cudaGetSymbolAddress((void**)&pk,    g_k);
    cudaGetSymbolAddress((void**)&pacc,  g_acc);
    cudaGetSymbolAddress((void**)&pcurA, g_cur);
    cudaGetSymbolAddress((void**)&pcurB, g_cur2);

    // init + graph preprocessing (once per call)
    k_init<<<16384, 256>>>(x);
    k_zero_pre<<<128, 256>>>();
    k_count<<<1024, 256>>>(row);
    k_dis<<<128, 256>>>();
    k_scanA<<<128, 256>>>();
    k_scanB<<<1, 128>>>();
    k_scanC<<<128, 256>>>();
    k_fill<<<1024, 256>>>(row, col);

    // projections + normalization + invariant attention terms
    k_gemm<<<dim3(4, 256), 256>>>(x, Wq_w, Wq_b, pq, NN, CDIM, DINc, 1.0f);
    k_gemm<<<dim3(4, 256), 256>>>(x, Wk_w, Wk_b, pk, NN, CDIM, DINc, 1.0f);
    k_norm<<<16384, 256>>>(pq);
    k_norm<<<16384, 256>>>(pk);
    k_colsum<<<dim3(32, 32), 128>>>();             // ksum (k is iteration-invariant)
    k_den<<<16384, 256>>>(nnod);

    // K_ORDER = 4 propagation steps, double-buffered cur
    float* cOld = pcurA;
    float* cNew = pcurB;
    for (int it = 0; it < 4; it++) {
        k_zero_vsum<<<16, 256>>>();
        k_kv<<<dim3(32, 8), 256>>>(cOld);          // kv partials + fused vsum
        k_kvreduce<<<2048, 256>>>();
        k_combine<<<dim3(32, 32), 256>>>(cOld, cNew);
        float* tmp = cOld; cOld = cNew; cNew = tmp;
    }

    // out = (acc @ Wo^T + b) / H
    k_gemm<<<dim3(1, 256), 256>>>(pacc, Wo_w, Wo_b, out, NN, DINc, CDIM, 0.25f);
}

// round 12
// speedup vs baseline: 2.0645x; 2.0645x over previous
#include <cuda_runtime.h>
#include <math.h>

// Problem dimensions (fixed by the dataset)
#define NN    32768      // total nodes B*NPG
#define BBg   8          // graphs
#define NPGc  4096       // nodes per graph
#define DINc  128
#define HHc   4
#define EEc   262144
#define CDIM  512        // H*DIN
#define BHc   32         // B*H

// ---------------- tf32 helpers ----------------
__device__ __forceinline__ float tf32r(float x) {
    unsigned r;
    asm("cvt.rna.tf32.f32 %0, %1;" : "=r"(r) : "f"(x));
    return __uint_as_float(r);
}
__device__ __forceinline__ void mma8(float* c, const unsigned* a, const unsigned* b) {
    asm volatile(
        "mma.sync.aligned.m16n8k8.row.col.f32.tf32.tf32.f32 "
        "{%0,%1,%2,%3},{%4,%5,%6,%7},{%8,%9},{%0,%1,%2,%3};\n"
        : "+f"(c[0]), "+f"(c[1]), "+f"(c[2]), "+f"(c[3])
        : "r"(a[0]), "r"(a[1]), "r"(a[2]), "r"(a[3]), "r"(b[0]), "r"(b[1]));
}
__device__ __forceinline__ unsigned fbits(float x) { return __float_as_uint(x); }

// ---------------- scratch (device globals: allocation-free) ----------------
__device__ float g_q   [NN*CDIM];
__device__ float g_k   [NN*CDIM];
__device__ float g_cur [NN*CDIM];
__device__ float g_acc [NN*CDIM];
__device__ float g_gcn [NN*CDIM];
__device__ float g_kvp [8*BHc*DINc*DINc]; // per-split partials
__device__ float g_kv  [BHc*DINc*DINc];
__device__ float g_vsum[BHc*DINc];
__device__ float g_ksum[BHc*DINc];
__device__ float g_den [NN*HHc];
__device__ int   g_deg   [NN];
__device__ float g_dis   [NN];
__device__ int   g_cursor[NN];
__device__ int   g_rowptr[NN];
__device__ int   g_incl  [NN];
__device__ int   g_bsum[128];
__device__ int   g_boff[128];
__device__ int   g_ecol[EEc];
__device__ float g_ew  [EEc];

// ---------------- init: cur = acc = broadcast(x over heads) ----------------
__global__ void k_init(const float* __restrict__ x) {
    int i = blockIdx.x * blockDim.x + threadIdx.x;     // float4 index over NN*CDIM/4
    int n  = i >> 7;            // 128 float4 per node
    int r  = i & 127;
    int d4 = r & 31;            // float4 within the 128-dim feature (head-replicated)
    float4 v = reinterpret_cast<const float4*>(x)[n * 32 + d4];
    reinterpret_cast<float4*>(g_cur)[i] = v;
    reinterpret_cast<float4*>(g_acc)[i] = v;
}

__global__ void k_zero_pre() {
    int i = blockIdx.x * blockDim.x + threadIdx.x;
    if (i < NN) { g_deg[i] = 0; g_cursor[i] = 0; }
    if (i < BHc * DINc) g_ksum[i] = 0.f;
}

__global__ void k_count(const int* __restrict__ row) {
    int e = blockIdx.x * blockDim.x + threadIdx.x;
    if (e < EEc) atomicAdd(&g_deg[row[e]], 1);
}

__global__ void k_dis() {
    int n = blockIdx.x * blockDim.x + threadIdx.x;
    if (n < NN) {
        int d = g_deg[n];
        g_dis[n] = (d > 0) ? (1.0f / sqrtf((float)d)) : 0.0f;
    }
}

// ---------------- prefix scan over deg -> rowptr (exclusive) ----------------
__global__ void k_scanA() {
    __shared__ int s[256];
    int t = threadIdx.x;
    int i = blockIdx.x * 256 + t;
    int v = g_deg[i];
    s[t] = v; __syncthreads();
    for (int off = 1; off < 256; off <<= 1) {
        int u = (t >= off) ? s[t - off] : 0;
        __syncthreads();
        s[t] += u;
        __syncthreads();
    }
    g_incl[i] = s[t];
    if (t == 255) g_bsum[blockIdx.x] = s[255];
}

__global__ void k_scanB() {
    __shared__ int s[128];
    int t = threadIdx.x;
    int v = g_bsum[t];
    s[t] = v; __syncthreads();
    for (int off = 1; off < 128; off <<= 1) {
        int u = (t >= off) ? s[t - off] : 0;
        __syncthreads();
        s[t] += u;
        __syncthreads();
    }
    g_boff[t] = s[t] - v;     // exclusive block offset
}

__global__ void k_scanC() {
    int i = blockIdx.x * blockDim.x + threadIdx.x;
    if (i < NN) g_rowptr[i] = g_incl[i] - g_deg[i] + g_boff[i >> 8];
}

__global__ void k_fill(const int* __restrict__ row, const int* __restrict__ col) {
    int e = blockIdx.x * blockDim.x + threadIdx.x;
    if (e < EEc) {
        int r = row[e], c = col[e];
        int pos = g_rowptr[r] + atomicAdd(&g_cursor[r], 1);
        g_ecol[pos] = c;
        g_ew[pos]   = g_dis[r] * g_dis[c];
    }
}

// ---------------- tf32 MMA GEMM: C[M,N] = scale*(A[M,K]@B[N,K]^T + bias[N]) ----------
// 128x128 block tile, 8 warps (2m x 4n), warp tile 64x32, K-chunk 32.
__global__ void __launch_bounds__(256)
k_gemm(const float* __restrict__ A, const float* __restrict__ B,
       const float* __restrict__ bias, float* __restrict__ C,
       int M, int N, int K, float scale) {
    __shared__ __align__(16) float sA[128 * 36];
    __shared__ __align__(16) float sB[128 * 36];
    int t  = threadIdx.x;
    int bm = blockIdx.y * 128;
    int bn = blockIdx.x * 128;
    int wid = t >> 5, lane = t & 31, gid = lane >> 2, tig = lane & 3;
    int wm = (wid & 1) * 64, wn = (wid >> 1) * 32;

    float c[4][4][4];
    #pragma unroll
    for (int i = 0; i < 4; i++)
        #pragma unroll
        for (int j = 0; j < 4; j++)
            #pragma unroll
            for (int r = 0; r < 4; r++) c[i][j][r] = 0.f;

    for (int kc = 0; kc < K; kc += 32) {
        #pragma unroll
        for (int l = 0; l < 4; l++) {
            int id = t + 256 * l;
            int row = id >> 3;
            int c4  = (id & 7) * 4;
            float4 v = *reinterpret_cast<const float4*>(&A[(bm + row) * K + kc + c4]);
            sA[row * 36 + c4 + 0] = tf32r(v.x);
            sA[row * 36 + c4 + 1] = tf32r(v.y);
            sA[row * 36 + c4 + 2] = tf32r(v.z);
            sA[row * 36 + c4 + 3] = tf32r(v.w);
            float4 w = *reinterpret_cast<const float4*>(&B[(bn + row) * K + kc + c4]);
            sB[row * 36 + c4 + 0] = tf32r(w.x);
            sB[row * 36 + c4 + 1] = tf32r(w.y);
            sB[row * 36 + c4 + 2] = tf32r(w.z);
            sB[row * 36 + c4 + 3] = tf32r(w.w);
        }
        __syncthreads();
        #pragma unroll
        for (int ks = 0; ks < 4; ks++) {
            int k0 = ks * 8;
            unsigned a[4][4], b[4][2];
            #pragma unroll
            for (int mt = 0; mt < 4; mt++) {
                int m = wm + 16 * mt + gid;
                a[mt][0] = fbits(sA[m * 36 + k0 + tig]);
                a[mt][1] = fbits(sA[(m + 8) * 36 + k0 + tig]);
                a[mt][2] = fbits(sA[m * 36 + k0 + tig + 4]);
                a[mt][3] = fbits(sA[(m + 8) * 36 + k0 + tig + 4]);
            }
            #pragma unroll
            for (int nt = 0; nt < 4; nt++) {
                int n = wn + 8 * nt + gid;
                b[nt][0] = fbits(sB[n * 36 + k0 + tig]);
                b[nt][1] = fbits(sB[n * 36 + k0 + tig + 4]);
            }
            #pragma unroll
            for (int mt = 0; mt < 4; mt++)
                #pragma unroll
                for (int nt = 0; nt < 4; nt++) mma8(c[mt][nt], a[mt], b[nt]);
        }
        __syncthreads();
    }

    #pragma unroll
    for (int mt = 0; mt < 4; mt++) {
        int r0 = bm + wm + 16 * mt + gid;
        #pragma unroll
        for (int nt = 0; nt < 4; nt++) {
            int col = bn + wn + 8 * nt + 2 * tig;
            float2 bb = *reinterpret_cast<const float2*>(&bias[col]);
            float2 o0, o1;
            o0.x = scale * (c[mt][nt][0] + bb.x);
            o0.y = scale * (c[mt][nt][1] + bb.y);
            o1.x = scale * (c[mt][nt][2] + bb.x);
            o1.y = scale * (c[mt][nt][3] + bb.y);
            *reinterpret_cast<float2*>(&C[r0 * N + col])       = o0;
            *reinterpret_cast<float2*>(&C[(r0 + 8) * N + col]) = o1;
        }
    }
}

// ---------------- L2-normalize rows of 128 (one warp per (n,h)) ----------------
__global__ void k_norm(float* __restrict__ buf) {
    int gt   = blockIdx.x * blockDim.x + threadIdx.x;
    int w    = gt >> 5;                 // warp over NN*HH rows
    int lane = threadIdx.x & 31;
    float4 v = reinterpret_cast<float4*>(buf)[w * 32 + lane];
    float ss = v.x * v.x + v.y * v.y + v.z * v.z + v.w * v.w;
    #pragma unroll
    for (int off = 16; off > 0; off >>= 1) ss += __shfl_xor_sync(0xffffffffu, ss, off);
    float r = 1.0f / sqrtf(ss);
    v.x *= r; v.y *= r; v.z *= r; v.w *= r;
    reinterpret_cast<float4*>(buf)[w * 32 + lane] = v;
}

// ---------------- ksum (once): column sums of normalized k per (b,h) ----------------
__global__ void k_colsum() {
    int bh = blockIdx.x;
    int b = bh >> 2, h = bh & 3;
    int nb = blockIdx.y * 128;
    int e = threadIdx.x;
    float s = 0.f;
    for (int n = 0; n < 128; n++)
        s += g_k[((b * NPGc + nb + n) * HHc + h) * DINc + e];
    atomicAdd(&g_ksum[bh * DINc + e], s);
}

// ---------------- den[n,h] = q . ksum + n_nodes (iteration-invariant) ----------------
__global__ void k_den(const int* __restrict__ n_nodes) {
    int gt   = blockIdx.x * blockDim.x + threadIdx.x;
    int w    = gt >> 5;                 // (n,h) index
    int lane = threadIdx.x & 31;
    int n = w >> 2, h = w & 3;
    int b = n >> 12;                    // NPG = 4096
    float4 q = reinterpret_cast<float4*>(g_q)[w * 32 + lane];
    float4 s = reinterpret_cast<float4*>(g_ksum)[((b << 2) | h) * 32 + lane];
    float d = q.x * s.x + q.y * s.y + q.z * s.z + q.w * s.w;
    #pragma unroll
    for (int off = 16; off > 0; off >>= 1) d += __shfl_xor_sync(0xffffffffu, d, off);
    if (lane == 0) g_den[w] = d + (float)n_nodes[b];
}

__global__ void k_zero_vsum() {
    int i = blockIdx.x * blockDim.x + threadIdx.x;
    if (i < BHc * DINc) g_vsum[i] = 0.f;
}

// ---------------- kv partials + fused vsum -------------------------------------
// Natural-layout smem [node][dim] (pad 136); transpose happens in fragment
// addressing: banks 8*tig+gid are conflict-free for both operands.
__global__ void __launch_bounds__(256) k_kv() {
    __shared__ __align__(16) float sK[32 * 136];
    __shared__ __align__(16) float sV[32 * 136];
    int bh = blockIdx.x, sp = blockIdx.y;
    int b = bh >> 2, h = bh & 3;
    int t = threadIdx.x;
    int wid = t >> 5, lane = t & 31, gid = lane >> 2, tig = lane & 3;
    int wm = (wid & 1) * 64, wn = (wid >> 1) * 32;
    int d4 = t & 31;                 // this thread's fixed 4-dim group

    float c[4][4][4];
    #pragma unroll
    for (int i = 0; i < 4; i++)
        #pragma unroll
        for (int j = 0; j < 4; j++)
            #pragma unroll
            for (int r = 0; r < 4; r++) c[i][j][r] = 0.f;
    float vs0 = 0.f, vs1 = 0.f, vs2 = 0.f, vs3 = 0.f;  // vsum partials (raw fp32)

    int nend = sp * 512 + 512;
    for (int nb = sp * 512; nb < nend; nb += 32) {
        #pragma unroll
        for (int l = 0; l < 4; l++) {
            int id = t + 256 * l;
            int nl = id >> 5;                    // node within chunk
            int fidx = ((b * NPGc + nb + nl) * HHc + h) * DINc + 4 * d4;
            float4 vk = *reinterpret_cast<const float4*>(&g_k[fidx]);
            float4 vv = *reinterpret_cast<const float4*>(&g_cur[fidx]);
            sK[nl * 136 + 4 * d4 + 0] = tf32r(vk.x);
            sK[nl * 136 + 4 * d4 + 1] = tf32r(vk.y);
            sK[nl * 136 + 4 * d4 + 2] = tf32r(vk.z);
            sK[nl * 136 + 4 * d4 + 3] = tf32r(vk.w);
            sV[nl * 136 + 4 * d4 + 0] = tf32r(vv.x);
            sV[nl * 136 + 4 * d4 + 1] = tf32r(vv.y);
            sV[nl * 136 + 4 * d4 + 2] = tf32r(vv.z);
            sV[nl * 136 + 4 * d4 + 3] = tf32r(vv.w);
            vs0 += vv.x; vs1 += vv.y; vs2 += vv.z; vs3 += vv.w;
        }
        __syncthreads();
        #pragma unroll
        for (int ks = 0; ks < 4; ks++) {
            int k0 = ks * 8;
            unsigned a[4][4], bf[4][2];
            #pragma unroll
            for (int mt = 0; mt < 4; mt++) {
                int m = wm + 16 * mt + gid;
                a[mt][0] = fbits(sK[(k0 + tig) * 136 + m]);
                a[mt][1] = fbits(sK[(k0 + tig) * 136 + m + 8]);
                a[mt][2] = fbits(sK[(k0 + tig + 4) * 136 + m]);
                a[mt][3] = fbits(sK[(k0 + tig + 4) * 136 + m + 8]);
            }
            #pragma unroll
            for (int nt = 0; nt < 4; nt++) {
                int e = wn + 8 * nt + gid;
                bf[nt][0] = fbits(sV[(k0 + tig) * 136 + e]);
                bf[nt][1] = fbits(sV[(k0 + tig + 4) * 136 + e]);
            }
            #pragma unroll
            for (int mt = 0; mt < 4; mt++)
                #pragma unroll
                for (int nt = 0; nt < 4; nt++) mma8(c[mt][nt], a[mt], bf[nt]);
        }
        __syncthreads();
    }

    // vsum partials -> global (REDG)
    atomicAdd(&g_vsum[bh * DINc + 4 * d4 + 0], vs0);
    atomicAdd(&g_vsum[bh * DINc + 4 * d4 + 1], vs1);
    atomicAdd(&g_vsum[bh * DINc + 4 * d4 + 2], vs2);
    atomicAdd(&g_vsum[bh * DINc + 4 * d4 + 3], vs3);

    float* dst = &g_kvp[(sp * BHc + bh) * (DINc * DINc)];
    #pragma unroll
    for (int mt = 0; mt < 4; mt++) {
        int r0 = wm + 16 * mt + gid;
        #pragma unroll
        for (int nt = 0; nt < 4; nt++) {
            int col = wn + 8 * nt + 2 * tig;
            *reinterpret_cast<float2*>(&dst[r0 * 128 + col]) =
                make_float2(c[mt][nt][0], c[mt][nt][1]);
            *reinterpret_cast<float2*>(&dst[(r0 + 8) * 128 + col]) =
                make_float2(c[mt][nt][2], c[mt][nt][3]);
        }
    }
}

__global__ void k_kvreduce() {
    int i = blockIdx.x * 256 + threadIdx.x;   // < 32*128*128 = 524288
    float s = 0.f;
    #pragma unroll
    for (int sp = 0; sp < 8; sp++) s += g_kvp[sp * (BHc * DINc * DINc) + i];
    g_kv[i] = s;
}

// ---------------- GCN gather: gcn[n] = sum_{e in CSR row n} w[e] * cur[col[e]] ----------------
__global__ void k_gcn() {
    int n = blockIdx.x;
    int t = threadIdx.x;             // 0..127, one float4 of the 512-wide feature
    int s = g_rowptr[n];
    int e = s + g_deg[n];
    float4 acc = make_float4(0.f, 0.f, 0.f, 0.f);
    for (int i = s; i < e; i++) {
        int   c = g_ecol[i];
        float w = g_ew[i];
        float4 v = reinterpret_cast<const float4*>(g_cur)[c * 128 + t];
        acc.x += w * v.x; acc.y += w * v.y; acc.z += w * v.z; acc.w += w * v.w;
    }
    reinterpret_cast<float4*>(g_gcn)[n * 128 + t] = acc;
}

// ---------------- combine: attn = (q@kv + vsum)/den; cur = .5*gcn + .5*attn; acc += cur
// Block tile: 128 nodes x 128 e, K = d = 128 in chunks of 32. tf32 MMA.
__global__ void __launch_bounds__(256) k_combine() {
    __shared__ __align__(16) float sQ [128 * 36];   // [node][d]
    __shared__ __align__(16) float sKV[32 * 136];   // [d][e]
    int bh = blockIdx.x, ch = blockIdx.y;
    int b = bh >> 2, h = bh & 3;
    int t = threadIdx.x;
    int wid = t >> 5, lane = t & 31, gid = lane >> 2, tig = lane & 3;
    int wm = (wid & 1) * 64, wn = (wid >> 1) * 32;
    int nbase = ch * 128;

    float c[4][4][4];
    #pragma unroll
    for (int i = 0; i < 4; i++)
        #pragma unroll
        for (int j = 0; j < 4; j++)
            #pragma unroll
            for (int r = 0; r < 4; r++) c[i][j][r] = 0.f;

    for (int kc = 0; kc < 128; kc += 32) {
        #pragma unroll
        for (int l = 0; l < 4; l++) {
            int id = t + 256 * l;
            int row = id >> 3;
            int c4  = (id & 7) * 4;
            float4 v = *reinterpret_cast<const float4*>(
                &g_q[((b * NPGc + nbase + row) * HHc + h) * DINc + kc + c4]);
            sQ[row * 36 + c4 + 0] = tf32r(v.x);
            sQ[row * 36 + c4 + 1] = tf32r(v.y);
            sQ[row * 36 + c4 + 2] = tf32r(v.z);
            sQ[row * 36 + c4 + 3] = tf32r(v.w);
            int drow = id >> 5;          // 0..31
            int e4   = (id & 31) * 4;
            float4 w = *reinterpret_cast<const float4*>(
                &g_kv[bh * (DINc * DINc) + (kc + drow) * 128 + e4]);
            sKV[drow * 136 + e4 + 0] = tf32r(w.x);
            sKV[drow * 136 + e4 + 1] = tf32r(w.y);
            sKV[drow * 136 + e4 + 2] = tf32r(w.z);
            sKV[drow * 136 + e4 + 3] = tf32r(w.w);
        }
        __syncthreads();
        #pragma unroll
        for (int ks = 0; ks < 4; ks++) {
            int k0 = ks * 8;
            unsigned a[4][4], bfr[4][2];
            #pragma unroll
            for (int mt = 0; mt < 4; mt++) {
                int m = wm + 16 * mt + gid;
                a[mt][0] = fbits(sQ[m * 36 + k0 + tig]);
                a[mt][1] = fbits(sQ[(m + 8) * 36 + k0 + tig]);
                a[mt][2] = fbits(sQ[m * 36 + k0 + tig + 4]);
                a[mt][3] = fbits(sQ[(m + 8) * 36 + k0 + tig + 4]);
            }
            #pragma unroll
            for (int nt = 0; nt < 4; nt++) {
                int e = wn + 8 * nt + gid;
                bfr[nt][0] = fbits(sKV[(k0 + tig) * 136 + e]);
                bfr[nt][1] = fbits(sKV[(k0 + tig + 4) * 136 + e]);
            }
            #pragma unroll
            for (int mt = 0; mt < 4; mt++)
                #pragma unroll
                for (int nt = 0; nt < 4; nt++) mma8(c[mt][nt], a[mt], bfr[nt]);
        }
        __syncthreads();
    }

    #pragma unroll
    for (int mt = 0; mt < 4; mt++) {
        int nl0 = nbase + wm + 16 * mt + gid;
        #pragma unroll
        for (int half = 0; half < 2; half++) {
            int nl = nl0 + half * 8;
            float inv = 1.0f / g_den[(b * NPGc + nl) * HHc + h];
            #pragma unroll
            for (int nt = 0; nt < 4; nt++) {
                int e = wn + 8 * nt + 2 * tig;
                int base = ((b * NPGc + nl) * HHc + h) * DINc + e;
                float cv0 = c[mt][nt][half * 2 + 0];
                float cv1 = c[mt][nt][half * 2 + 1];
                float2 vs = *reinterpret_cast<const float2*>(&g_vsum[bh * DINc + e]);
                float2 gc = *reinterpret_cast<const float2*>(&g_gcn[base]);
                float2 ac = *reinterpret_cast<const float2*>(&g_acc[base]);
                float o0 = 0.5f * (gc.x + (cv0 + vs.x) * inv);
                float o1 = 0.5f * (gc.y + (cv1 + vs.y) * inv);
                *reinterpret_cast<float2*>(&g_cur[base]) = make_float2(o0, o1);
                *reinterpret_cast<float2*>(&g_acc[base]) = make_float2(ac.x + o0, ac.y + o1);
            }
        }
    }
}

// ---------------- launcher ----------------
extern "C" void kernel_launch(void* const* d_in, const int* in_sizes, int n_in,
                              void* d_out, int out_size) {
    const float* x    = (const float*)d_in[0];
    const float* Wq_w = (const float*)d_in[1];
    const float* Wq_b = (const float*)d_in[2];
    const float* Wk_w = (const float*)d_in[3];
    const float* Wk_b = (const float*)d_in[4];
    const float* Wo_w = (const float*)d_in[5];
    const float* Wo_b = (const float*)d_in[6];
    const int*   edge = (const int*)d_in[7];
    const int*   nnod = (const int*)d_in[8];
    const int* row = edge;
    const int* col = edge + EEc;
    float* out = (float*)d_out;

    float *pq, *pk, *pacc;
    cudaGetSymbolAddress((void**)&pq,   g_q);
    cudaGetSymbolAddress((void**)&pk,   g_k);
    cudaGetSymbolAddress((void**)&pacc, g_acc);

    // init + graph preprocessing (once per call)
    k_init<<<16384, 256>>>(x);
    k_zero_pre<<<128, 256>>>();
    k_count<<<1024, 256>>>(row);
    k_dis<<<128, 256>>>();
    k_scanA<<<128, 256>>>();
    k_scanB<<<1, 128>>>();
    k_scanC<<<128, 256>>>();
    k_fill<<<1024, 256>>>(row, col);

    // projections + normalization + invariant attention terms
    k_gemm<<<dim3(4, 256), 256>>>(x, Wq_w, Wq_b, pq, NN, CDIM, DINc, 1.0f);
    k_gemm<<<dim3(4, 256), 256>>>(x, Wk_w, Wk_b, pk, NN, CDIM, DINc, 1.0f);
    k_norm<<<16384, 256>>>(pq);
    k_norm<<<16384, 256>>>(pk);
    k_colsum<<<dim3(32, 32), 128>>>();             // ksum (k is iteration-invariant)
    k_den<<<16384, 256>>>(nnod);

    // K_ORDER = 4 propagation steps
    for (int it = 0; it < 4; it++) {
        k_zero_vsum<<<16, 256>>>();
        k_kv<<<dim3(32, 8), 256>>>();              // kv partials + fused vsum
        k_kvreduce<<<2048, 256>>>();
        k_gcn<<<32768, 128>>>();
        k_combine<<<dim3(32, 32), 256>>>();
    }

    // out = (acc @ Wo^T + b) / H
    k_gemm<<<dim3(1, 256), 256>>>(pacc, Wo_w, Wo_b, out, NN, DINc, CDIM, 0.25f);
}

// round 13
// speedup vs baseline: 2.2135x; 1.0722x over previous
#include <cuda_runtime.h>
#include <math.h>

// Problem dimensions (fixed by the dataset)
#define NN    32768      // total nodes B*NPG
#define BBg   8          // graphs
#define NPGc  4096       // nodes per graph
#define DINc  128
#define HHc   4
#define EEc   262144
#define CDIM  512        // H*DIN
#define BHc   32         // B*H

// ---------------- tf32 helpers ----------------
__device__ __forceinline__ float tf32r(float x) {
    unsigned r;
    asm("cvt.rna.tf32.f32 %0, %1;" : "=r"(r) : "f"(x));
    return __uint_as_float(r);
}
__device__ __forceinline__ void mma8(float* c, const unsigned* a, const unsigned* b) {
    asm volatile(
        "mma.sync.aligned.m16n8k8.row.col.f32.tf32.tf32.f32 "
        "{%0,%1,%2,%3},{%4,%5,%6,%7},{%8,%9},{%0,%1,%2,%3};\n"
        : "+f"(c[0]), "+f"(c[1]), "+f"(c[2]), "+f"(c[3])
        : "r"(a[0]), "r"(a[1]), "r"(a[2]), "r"(a[3]), "r"(b[0]), "r"(b[1]));
}
__device__ __forceinline__ unsigned fbits(float x) { return __float_as_uint(x); }

// ---------------- scratch (device globals: allocation-free) ----------------
__device__ float g_q   [NN*CDIM];
__device__ float g_k   [NN*CDIM];
__device__ float g_c0  [NN*CDIM];   // cur_0 = broadcast(x)
__device__ float g_c1  [NN*CDIM];   // cur_1..cur_4 (kept for deferred acc)
__device__ float g_c2  [NN*CDIM];
__device__ float g_c3  [NN*CDIM];
__device__ float g_c4  [NN*CDIM];
__device__ float g_gcn [NN*CDIM];
__device__ float g_kvp [8*BHc*DINc*DINc]; // per-split partials
__device__ float g_kv  [BHc*DINc*DINc];
__device__ float g_vsum[BHc*DINc];
__device__ float g_ksum[BHc*DINc];
__device__ float g_den [NN*HHc];
__device__ int   g_deg   [NN];
__device__ float g_dis   [NN];
__device__ int   g_cursor[NN];
__device__ int   g_rowptr[NN];
__device__ int   g_incl  [NN];
__device__ int   g_bsum[128];
__device__ int   g_boff[128];
__device__ int   g_ecol[EEc];
__device__ float g_ew  [EEc];

// ---------------- init: cur0 = broadcast(x over heads) ----------------
__global__ void k_init(const float* __restrict__ x) {
    int i = blockIdx.x * blockDim.x + threadIdx.x;     // float4 index over NN*CDIM/4
    int n  = i >> 7;            // 128 float4 per node
    int r  = i & 127;
    int d4 = r & 31;            // float4 within the 128-dim feature (head-replicated)
    float4 v = reinterpret_cast<const float4*>(x)[n * 32 + d4];
    reinterpret_cast<float4*>(g_c0)[i] = v;
}

__global__ void k_zero_pre() {
    int i = blockIdx.x * blockDim.x + threadIdx.x;
    if (i < NN) { g_deg[i] = 0; g_cursor[i] = 0; }
    if (i < BHc * DINc) g_ksum[i] = 0.f;
}

__global__ void k_count(const int* __restrict__ row) {
    int e = blockIdx.x * blockDim.x + threadIdx.x;
    if (e < EEc) atomicAdd(&g_deg[row[e]], 1);
}

__global__ void k_dis() {
    int n = blockIdx.x * blockDim.x + threadIdx.x;
    if (n < NN) {
        int d = g_deg[n];
        g_dis[n] = (d > 0) ? (1.0f / sqrtf((float)d)) : 0.0f;
    }
}

// ---------------- prefix scan over deg -> rowptr (exclusive) ----------------
__global__ void k_scanA() {
    __shared__ int s[256];
    int t = threadIdx.x;
    int i = blockIdx.x * 256 + t;
    int v = g_deg[i];
    s[t] = v; __syncthreads();
    for (int off = 1; off < 256; off <<= 1) {
        int u = (t >= off) ? s[t - off] : 0;
        __syncthreads();
        s[t] += u;
        __syncthreads();
    }
    g_incl[i] = s[t];
    if (t == 255) g_bsum[blockIdx.x] = s[255];
}

__global__ void k_scanB() {
    __shared__ int s[128];
    int t = threadIdx.x;
    int v = g_bsum[t];
    s[t] = v; __syncthreads();
    for (int off = 1; off < 128; off <<= 1) {
        int u = (t >= off) ? s[t - off] : 0;
        __syncthreads();
        s[t] += u;
        __syncthreads();
    }
    g_boff[t] = s[t] - v;     // exclusive block offset
}

__global__ void k_scanC() {
    int i = blockIdx.x * blockDim.x + threadIdx.x;
    if (i < NN) g_rowptr[i] = g_incl[i] - g_deg[i] + g_boff[i >> 8];
}

__global__ void k_fill(const int* __restrict__ row, const int* __restrict__ col) {
    int e = blockIdx.x * blockDim.x + threadIdx.x;
    if (e < EEc) {
        int r = row[e], c = col[e];
        int pos = g_rowptr[r] + atomicAdd(&g_cursor[r], 1);
        g_ecol[pos] = c;
        g_ew[pos]   = g_dis[r] * g_dis[c];
    }
}

// ---------------- tf32 MMA GEMM: C[M,N] = scale*(A[M,K]@B[N,K]^T + bias[N]) ----------
// 128x128 block tile, 8 warps (2m x 4n), warp tile 64x32, K-chunk 32.
// normalize=1: each row of the 128-col tile is a full head vector -> L2-normalize
// (bias added first) in the epilogue.
__global__ void __launch_bounds__(256)
k_gemm(const float* __restrict__ A, const float* __restrict__ B,
       const float* __restrict__ bias, float* __restrict__ C,
       int M, int N, int K, float scale, int normalize) {
    __shared__ __align__(16) float sA[128 * 36];
    __shared__ __align__(16) float sB[128 * 36];
    int t  = threadIdx.x;
    int bm = blockIdx.y * 128;
    int bn = blockIdx.x * 128;
    int wid = t >> 5, lane = t & 31, gid = lane >> 2, tig = lane & 3;
    int wm = (wid & 1) * 64, wn = (wid >> 1) * 32;

    float c[4][4][4];
    #pragma unroll
    for (int i = 0; i < 4; i++)
        #pragma unroll
        for (int j = 0; j < 4; j++)
            #pragma unroll
            for (int r = 0; r < 4; r++) c[i][j][r] = 0.f;

    for (int kc = 0; kc < K; kc += 32) {
        #pragma unroll
        for (int l = 0; l < 4; l++) {
            int id = t + 256 * l;
            int row = id >> 3;
            int c4  = (id & 7) * 4;
            float4 v = *reinterpret_cast<const float4*>(&A[(bm + row) * K + kc + c4]);
            sA[row * 36 + c4 + 0] = tf32r(v.x);
            sA[row * 36 + c4 + 1] = tf32r(v.y);
            sA[row * 36 + c4 + 2] = tf32r(v.z);
            sA[row * 36 + c4 + 3] = tf32r(v.w);
            float4 w = *reinterpret_cast<const float4*>(&B[(bn + row) * K + kc + c4]);
            sB[row * 36 + c4 + 0] = tf32r(w.x);
            sB[row * 36 + c4 + 1] = tf32r(w.y);
            sB[row * 36 + c4 + 2] = tf32r(w.z);
            sB[row * 36 + c4 + 3] = tf32r(w.w);
        }
        __syncthreads();
        #pragma unroll
        for (int ks = 0; ks < 4; ks++) {
            int k0 = ks * 8;
            unsigned a[4][4], b[4][2];
            #pragma unroll
            for (int mt = 0; mt < 4; mt++) {
                int m = wm + 16 * mt + gid;
                a[mt][0] = fbits(sA[m * 36 + k0 + tig]);
                a[mt][1] = fbits(sA[(m + 8) * 36 + k0 + tig]);
                a[mt][2] = fbits(sA[m * 36 + k0 + tig + 4]);
                a[mt][3] = fbits(sA[(m + 8) * 36 + k0 + tig + 4]);
            }
            #pragma unroll
            for (int nt = 0; nt < 4; nt++) {
                int n = wn + 8 * nt + gid;
                b[nt][0] = fbits(sB[n * 36 + k0 + tig]);
                b[nt][1] = fbits(sB[n * 36 + k0 + tig + 4]);
            }
            #pragma unroll
            for (int mt = 0; mt < 4; mt++)
                #pragma unroll
                for (int nt = 0; nt < 4; nt++) mma8(c[mt][nt], a[mt], b[nt]);
        }
        __syncthreads();
    }

    // bias first (normalization is applied to xW + b)
    #pragma unroll
    for (int nt = 0; nt < 4; nt++) {
        float2 bb = *reinterpret_cast<const float2*>(&bias[bn + wn + 8 * nt + 2 * tig]);
        #pragma unroll
        for (int mt = 0; mt < 4; mt++) {
            c[mt][nt][0] += bb.x; c[mt][nt][1] += bb.y;
            c[mt][nt][2] += bb.x; c[mt][nt][3] += bb.y;
        }
    }

    if (normalize) {
        float* sred = sA;            // [row][4] partials
        float* sinv = sA + 512;      // [row]
        #pragma unroll
        for (int mt = 0; mt < 4; mt++) {
            #pragma unroll
            for (int half = 0; half < 2; half++) {
                float ss = 0.f;
                #pragma unroll
                for (int nt = 0; nt < 4; nt++) {
                    float v0 = c[mt][nt][half * 2 + 0];
                    float v1 = c[mt][nt][half * 2 + 1];
                    ss += v0 * v0 + v1 * v1;
                }
                ss += __shfl_xor_sync(0xffffffffu, ss, 1);
                ss += __shfl_xor_sync(0xffffffffu, ss, 2);
                if (tig == 0)
                    sred[(wm + 16 * mt + gid + 8 * half) * 4 + (wn >> 5)] = ss;
            }
        }
        __syncthreads();
        if (t < 128)
            sinv[t] = 1.0f / sqrtf(sred[t * 4] + sred[t * 4 + 1] +
                                   sred[t * 4 + 2] + sred[t * 4 + 3]);
        __syncthreads();
        #pragma unroll
        for (int mt = 0; mt < 4; mt++) {
            #pragma unroll
            for (int half = 0; half < 2; half++) {
                float iv = sinv[wm + 16 * mt + gid + 8 * half];
                #pragma unroll
                for (int nt = 0; nt < 4; nt++) {
                    c[mt][nt][half * 2 + 0] *= iv;
                    c[mt][nt][half * 2 + 1] *= iv;
                }
            }
        }
    }

    #pragma unroll
    for (int mt = 0; mt < 4; mt++) {
        int r0 = bm + wm + 16 * mt + gid;
        #pragma unroll
        for (int nt = 0; nt < 4; nt++) {
            int col = bn + wn + 8 * nt + 2 * tig;
            float2 o0, o1;
            o0.x = scale * c[mt][nt][0];
            o0.y = scale * c[mt][nt][1];
            o1.x = scale * c[mt][nt][2];
            o1.y = scale * c[mt][nt][3];
            *reinterpret_cast<float2*>(&C[r0 * N + col])       = o0;
            *reinterpret_cast<float2*>(&C[(r0 + 8) * N + col]) = o1;
        }
    }
}

// ---------------- final GEMM with deferred acc: A = bc(x) + c1 + c2 + c3 + c4 ----------
__global__ void __launch_bounds__(256)
k_gemmsum(const float* __restrict__ x, const float* __restrict__ B,
          const float* __restrict__ bias, float* __restrict__ C,
          float scale) {
    const int N = DINc, K = CDIM;
    __shared__ __align__(16) float sA[128 * 36];
    __shared__ __align__(16) float sB[128 * 36];
    int t  = threadIdx.x;
    int bm = blockIdx.y * 128;
    int wid = t >> 5, lane = t & 31, gid = lane >> 2, tig = lane & 3;
    int wm = (wid & 1) * 64, wn = (wid >> 1) * 32;

    float c[4][4][4];
    #pragma unroll
    for (int i = 0; i < 4; i++)
        #pragma unroll
        for (int j = 0; j < 4; j++)
            #pragma unroll
            for (int r = 0; r < 4; r++) c[i][j][r] = 0.f;

    for (int kc = 0; kc < K; kc += 32) {
        #pragma unroll
        for (int l = 0; l < 4; l++) {
            int id = t + 256 * l;
            int row = id >> 3;
            int c4  = (id & 7) * 4;
            int gr  = bm + row;
            int kk  = kc + c4;
            float4 v  = *reinterpret_cast<const float4*>(&x[gr * DINc + (kk & 127)]);
            float4 a1 = *reinterpret_cast<const float4*>(&g_c1[gr * CDIM + kk]);
            float4 a2 = *reinterpret_cast<const float4*>(&g_c2[gr * CDIM + kk]);
            float4 a3 = *reinterpret_cast<const float4*>(&g_c3[gr * CDIM + kk]);
            float4 a4 = *reinterpret_cast<const float4*>(&g_c4[gr * CDIM + kk]);
            v.x += a1.x + a2.x + a3.x + a4.x;
            v.y += a1.y + a2.y + a3.y + a4.y;
            v.z += a1.z + a2.z + a3.z + a4.z;
            v.w += a1.w + a2.w + a3.w + a4.w;
            sA[row * 36 + c4 + 0] = tf32r(v.x);
            sA[row * 36 + c4 + 1] = tf32r(v.y);
            sA[row * 36 + c4 + 2] = tf32r(v.z);
            sA[row * 36 + c4 + 3] = tf32r(v.w);
            float4 w = *reinterpret_cast<const float4*>(&B[row * K + kk]);
            sB[row * 36 + c4 + 0] = tf32r(w.x);
            sB[row * 36 + c4 + 1] = tf32r(w.y);
            sB[row * 36 + c4 + 2] = tf32r(w.z);
            sB[row * 36 + c4 + 3] = tf32r(w.w);
        }
        __syncthreads();
        #pragma unroll
        for (int ks = 0; ks < 4; ks++) {
            int k0 = ks * 8;
            unsigned a[4][4], b[4][2];
            #pragma unroll
            for (int mt = 0; mt < 4; mt++) {
                int m = wm + 16 * mt + gid;
                a[mt][0] = fbits(sA[m * 36 + k0 + tig]);
                a[mt][1] = fbits(sA[(m + 8) * 36 + k0 + tig]);
                a[mt][2] = fbits(sA[m * 36 + k0 + tig + 4]);
                a[mt][3] = fbits(sA[(m + 8) * 36 + k0 + tig + 4]);
            }
            #pragma unroll
            for (int nt = 0; nt < 4; nt++) {
                int n = wn + 8 * nt + gid;
                b[nt][0] = fbits(sB[n * 36 + k0 + tig]);
                b[nt][1] = fbits(sB[n * 36 + k0 + tig + 4]);
            }
            #pragma unroll
            for (int mt = 0; mt < 4; mt++)
                #pragma unroll
                for (int nt = 0; nt < 4; nt++) mma8(c[mt][nt], a[mt], b[nt]);
        }
        __syncthreads();
    }

    #pragma unroll
    for (int mt = 0; mt < 4; mt++) {
        int r0 = bm + wm + 16 * mt + gid;
        #pragma unroll
        for (int nt = 0; nt < 4; nt++) {
            int col = wn + 8 * nt + 2 * tig;
            float2 bb = *reinterpret_cast<const float2*>(&bias[col]);
            float2 o0, o1;
            o0.x = scale * (c[mt][nt][0] + bb.x);
            o0.y = scale * (c[mt][nt][1] + bb.y);
            o1.x = scale * (c[mt][nt][2] + bb.x);
            o1.y = scale * (c[mt][nt][3] + bb.y);
            *reinterpret_cast<float2*>(&C[r0 * N + col])       = o0;
            *reinterpret_cast<float2*>(&C[(r0 + 8) * N + col]) = o1;
        }
    }
}

// ---------------- ksum (once): column sums of normalized k per (b,h) ----------------
__global__ void k_colsum() {
    int bh = blockIdx.x;
    int b = bh >> 2, h = bh & 3;
    int nb = blockIdx.y * 128;
    int e = threadIdx.x;
    float s = 0.f;
    for (int n = 0; n < 128; n++)
        s += g_k[((b * NPGc + nb + n) * HHc + h) * DINc + e];
    atomicAdd(&g_ksum[bh * DINc + e], s);
}

// ---------------- den[n,h] = q . ksum + n_nodes (iteration-invariant) ----------------
__global__ void k_den(const int* __restrict__ n_nodes) {
    int gt   = blockIdx.x * blockDim.x + threadIdx.x;
    int w    = gt >> 5;                 // (n,h) index
    int lane = threadIdx.x & 31;
    int n = w >> 2, h = w & 3;
    int b = n >> 12;                    // NPG = 4096
    float4 q = reinterpret_cast<float4*>(g_q)[w * 32 + lane];
    float4 s = reinterpret_cast<float4*>(g_ksum)[((b << 2) | h) * 32 + lane];
    float d = q.x * s.x + q.y * s.y + q.z * s.z + q.w * s.w;
    #pragma unroll
    for (int off = 16; off > 0; off >>= 1) d += __shfl_xor_sync(0xffffffffu, d, off);
    if (lane == 0) g_den[w] = d + (float)n_nodes[b];
}

__global__ void k_zero_vsum() {
    int i = blockIdx.x * blockDim.x + threadIdx.x;
    if (i < BHc * DINc) g_vsum[i] = 0.f;
}

// ---------------- kv partials + fused vsum -------------------------------------
// Natural-layout smem [node][dim] (pad 136); transpose happens in fragment
// addressing: banks 8*tig+gid are conflict-free for both operands.
__global__ void __launch_bounds__(256) k_kv(const float* __restrict__ cur) {
    __shared__ __align__(16) float sK[32 * 136];
    __shared__ __align__(16) float sV[32 * 136];
    int bh = blockIdx.x, sp = blockIdx.y;
    int b = bh >> 2, h = bh & 3;
    int t = threadIdx.x;
    int wid = t >> 5, lane = t & 31, gid = lane >> 2, tig = lane & 3;
    int wm = (wid & 1) * 64, wn = (wid >> 1) * 32;
    int d4 = t & 31;                 // this thread's fixed 4-dim group

    float c[4][4][4];
    #pragma unroll
    for (int i = 0; i < 4; i++)
        #pragma unroll
        for (int j = 0; j < 4; j++)
            #pragma unroll
            for (int r = 0; r < 4; r++) c[i][j][r] = 0.f;
    float vs0 = 0.f, vs1 = 0.f, vs2 = 0.f, vs3 = 0.f;  // vsum partials (raw fp32)

    int nend = sp * 512 + 512;
    for (int nb = sp * 512; nb < nend; nb += 32) {
        #pragma unroll
        for (int l = 0; l < 4; l++) {
            int id = t + 256 * l;
            int nl = id >> 5;                    // node within chunk
            int fidx = ((b * NPGc + nb + nl) * HHc + h) * DINc + 4 * d4;
            float4 vk = *reinterpret_cast<const float4*>(&g_k[fidx]);
            float4 vv = *reinterpret_cast<const float4*>(&cur[fidx]);
            sK[nl * 136 + 4 * d4 + 0] = tf32r(vk.x);
            sK[nl * 136 + 4 * d4 + 1] = tf32r(vk.y);
            sK[nl * 136 + 4 * d4 + 2] = tf32r(vk.z);
            sK[nl * 136 + 4 * d4 + 3] = tf32r(vk.w);
            sV[nl * 136 + 4 * d4 + 0] = tf32r(vv.x);
            sV[nl * 136 + 4 * d4 + 1] = tf32r(vv.y);
            sV[nl * 136 + 4 * d4 + 2] = tf32r(vv.z);
            sV[nl * 136 + 4 * d4 + 3] = tf32r(vv.w);
            vs0 += vv.x; vs1 += vv.y; vs2 += vv.z; vs3 += vv.w;
        }
        __syncthreads();
        #pragma unroll
        for (int ks = 0; ks < 4; ks++) {
            int k0 = ks * 8;
            unsigned a[4][4], bf[4][2];
            #pragma unroll
            for (int mt = 0; mt < 4; mt++) {
                int m = wm + 16 * mt + gid;
                a[mt][0] = fbits(sK[(k0 + tig) * 136 + m]);
                a[mt][1] = fbits(sK[(k0 + tig) * 136 + m + 8]);
                a[mt][2] = fbits(sK[(k0 + tig + 4) * 136 + m]);
                a[mt][3] = fbits(sK[(k0 + tig + 4) * 136 + m + 8]);
            }
            #pragma unroll
            for (int nt = 0; nt < 4; nt++) {
                int e = wn + 8 * nt + gid;
                bf[nt][0] = fbits(sV[(k0 + tig) * 136 + e]);
                bf[nt][1] = fbits(sV[(k0 + tig + 4) * 136 + e]);
            }
            #pragma unroll
            for (int mt = 0; mt < 4; mt++)
                #pragma unroll
                for (int nt = 0; nt < 4; nt++) mma8(c[mt][nt], a[mt], bf[nt]);
        }
        __syncthreads();
    }

    // vsum partials -> global (REDG)
    atomicAdd(&g_vsum[bh * DINc + 4 * d4 + 0], vs0);
    atomicAdd(&g_vsum[bh * DINc + 4 * d4 + 1], vs1);
    atomicAdd(&g_vsum[bh * DINc + 4 * d4 + 2], vs2);
    atomicAdd(&g_vsum[bh * DINc + 4 * d4 + 3], vs3);

    float* dst = &g_kvp[(sp * BHc + bh) * (DINc * DINc)];
    #pragma unroll
    for (int mt = 0; mt < 4; mt++) {
        int r0 = wm + 16 * mt + gid;
        #pragma unroll
        for (int nt = 0; nt < 4; nt++) {
            int col = wn + 8 * nt + 2 * tig;
            *reinterpret_cast<float2*>(&dst[r0 * 128 + col]) =
                make_float2(c[mt][nt][0], c[mt][nt][1]);
            *reinterpret_cast<float2*>(&dst[(r0 + 8) * 128 + col]) =
                make_float2(c[mt][nt][2], c[mt][nt][3]);
        }
    }
}

__global__ void k_kvreduce() {
    int i = blockIdx.x * 256 + threadIdx.x;   // < 32*128*128 = 524288
    float s = 0.f;
    #pragma unroll
    for (int sp = 0; sp < 8; sp++) s += g_kvp[sp * (BHc * DINc * DINc) + i];
    g_kv[i] = s;
}

// ---------------- GCN gather: gcn[n] = sum_{e in CSR row n} w[e] * cur[col[e]] ----------------
__global__ void k_gcn(const float* __restrict__ cur) {
    int n = blockIdx.x;
    int t = threadIdx.x;             // 0..127, one float4 of the 512-wide feature
    int s = g_rowptr[n];
    int e = s + g_deg[n];
    float4 acc = make_float4(0.f, 0.f, 0.f, 0.f);
    for (int i = s; i < e; i++) {
        int   c = g_ecol[i];
        float w = g_ew[i];
        float4 v = reinterpret_cast<const float4*>(cur)[c * 128 + t];
        acc.x += w * v.x; acc.y += w * v.y; acc.z += w * v.z; acc.w += w * v.w;
    }
    reinterpret_cast<float4*>(g_gcn)[n * 128 + t] = acc;
}

// ---------------- combine: attn = (q@kv + vsum)/den; curNew = .5*gcn + .5*attn
// Block tile: 128 nodes x 128 e, K = d = 128 in chunks of 32. tf32 MMA.
__global__ void __launch_bounds__(256) k_combine(float* __restrict__ curNew) {
    __shared__ __align__(16) float sQ [128 * 36];   // [node][d]
    __shared__ __align__(16) float sKV[32 * 136];   // [d][e]
    int bh = blockIdx.x, ch = blockIdx.y;
    int b = bh >> 2, h = bh & 3;
    int t = threadIdx.x;
    int wid = t >> 5, lane = t & 31, gid = lane >> 2, tig = lane & 3;
    int wm = (wid & 1) * 64, wn = (wid >> 1) * 32;
    int nbase = ch * 128;

    float c[4][4][4];
    #pragma unroll
    for (int i = 0; i < 4; i++)
        #pragma unroll
        for (int j = 0; j < 4; j++)
            #pragma unroll
            for (int r = 0; r < 4; r++) c[i][j][r] = 0.f;

    for (int kc = 0; kc < 128; kc += 32) {
        #pragma unroll
        for (int l = 0; l < 4; l++) {
            int id = t + 256 * l;
            int row = id >> 3;
            int c4  = (id & 7) * 4;
            float4 v = *reinterpret_cast<const float4*>(
                &g_q[((b * NPGc + nbase + row) * HHc + h) * DINc + kc + c4]);
            sQ[row * 36 + c4 + 0] = tf32r(v.x);
            sQ[row * 36 + c4 + 1] = tf32r(v.y);
            sQ[row * 36 + c4 + 2] = tf32r(v.z);
            sQ[row * 36 + c4 + 3] = tf32r(v.w);
            int drow = id >> 5;          // 0..31
            int e4   = (id & 31) * 4;
            float4 w = *reinterpret_cast<const float4*>(
                &g_kv[bh * (DINc * DINc) + (kc + drow) * 128 + e4]);
            sKV[drow * 136 + e4 + 0] = tf32r(w.x);
            sKV[drow * 136 + e4 + 1] = tf32r(w.y);
            sKV[drow * 136 + e4 + 2] = tf32r(w.z);
            sKV[drow * 136 + e4 + 3] = tf32r(w.w);
        }
        __syncthreads();
        #pragma unroll
        for (int ks = 0; ks < 4; ks++) {
            int k0 = ks * 8;
            unsigned a[4][4], bfr[4][2];
            #pragma unroll
            for (int mt = 0; mt < 4; mt++) {
                int m = wm + 16 * mt + gid;
                a[mt][0] = fbits(sQ[m * 36 + k0 + tig]);
                a[mt][1] = fbits(sQ[(m + 8) * 36 + k0 + tig]);
                a[mt][2] = fbits(sQ[m * 36 + k0 + tig + 4]);
                a[mt][3] = fbits(sQ[(m + 8) * 36 + k0 + tig + 4]);
            }
            #pragma unroll
            for (int nt = 0; nt < 4; nt++) {
                int e = wn + 8 * nt + gid;
                bfr[nt][0] = fbits(sKV[(k0 + tig) * 136 + e]);
                bfr[nt][1] = fbits(sKV[(k0 + tig + 4) * 136 + e]);
            }
            #pragma unroll
            for (int mt = 0; mt < 4; mt++)
                #pragma unroll
                for (int nt = 0; nt < 4; nt++) mma8(c[mt][nt], a[mt], bfr[nt]);
        }
        __syncthreads();
    }

    #pragma unroll
    for (int mt = 0; mt < 4; mt++) {
        int nl0 = nbase + wm + 16 * mt + gid;
        #pragma unroll
        for (int half = 0; half < 2; half++) {
            int nl = nl0 + half * 8;
            float inv = 1.0f / g_den[(b * NPGc + nl) * HHc + h];
            #pragma unroll
            for (int nt = 0; nt < 4; nt++) {
                int e = wn + 8 * nt + 2 * tig;
                int base = ((b * NPGc + nl) * HHc + h) * DINc + e;
                float cv0 = c[mt][nt][half * 2 + 0];
                float cv1 = c[mt][nt][half * 2 + 1];
                float2 vs = *reinterpret_cast<const float2*>(&g_vsum[bh * DINc + e]);
                float2 gc = *reinterpret_cast<const float2*>(&g_gcn[base]);
                float o0 = 0.5f * (gc.x + (cv0 + vs.x) * inv);
                float o1 = 0.5f * (gc.y + (cv1 + vs.y) * inv);
                *reinterpret_cast<float2*>(&curNew[base]) = make_float2(o0, o1);
            }
        }
    }
}

// ---------------- launcher ----------------
extern "C" void kernel_launch(void* const* d_in, const int* in_sizes, int n_in,
                              void* d_out, int out_size) {
    const float* x    = (const float*)d_in[0];
    const float* Wq_w = (const float*)d_in[1];
    const float* Wq_b = (const float*)d_in[2];
    const float* Wk_w = (const float*)d_in[3];
    const float* Wk_b = (const float*)d_in[4];
    const float* Wo_w = (const float*)d_in[5];
    const float* Wo_b = (const float*)d_in[6];
    const int*   edge = (const int*)d_in[7];
    const int*   nnod = (const int*)d_in[8];
    const int* row = edge;
    const int* col = edge + EEc;
    float* out = (float*)d_out;

    float *pq, *pk, *pc0, *pc1, *pc2, *pc3, *pc4;
    cudaGetSymbolAddress((void**)&pq,  g_q);
    cudaGetSymbolAddress((void**)&pk,  g_k);
    cudaGetSymbolAddress((void**)&pc0, g_c0);
    cudaGetSymbolAddress((void**)&pc1, g_c1);
    cudaGetSymbolAddress((void**)&pc2, g_c2);
    cudaGetSymbolAddress((void**)&pc3, g_c3);
    cudaGetSymbolAddress((void**)&pc4, g_c4);
    float* bufs[5] = {pc0, pc1, pc2, pc3, pc4};

    // init + graph preprocessing (once per call)
    k_init<<<16384, 256>>>(x);
    k_zero_pre<<<128, 256>>>();
    k_count<<<1024, 256>>>(row);
    k_dis<<<128, 256>>>();
    k_scanA<<<128, 256>>>();
    k_scanB<<<1, 128>>>();
    k_scanC<<<128, 256>>>();
    k_fill<<<1024, 256>>>(row, col);

    // projections (normalize fused into epilogue) + invariant attention terms
    k_gemm<<<dim3(4, 256), 256>>>(x, Wq_w, Wq_b, pq, NN, CDIM, DINc, 1.0f, 1);
    k_gemm<<<dim3(4, 256), 256>>>(x, Wk_w, Wk_b, pk, NN, CDIM, DINc, 1.0f, 1);
    k_colsum<<<dim3(32, 32), 128>>>();             // ksum (k is iteration-invariant)
    k_den<<<16384, 256>>>(nnod);

    // K_ORDER = 4 propagation steps; cur_t kept in separate buffers (deferred acc)
    for (int it = 0; it < 4; it++) {
        k_zero_vsum<<<16, 256>>>();
        k_kv<<<dim3(32, 8), 256>>>(bufs[it]);      // kv partials + fused vsum
        k_kvreduce<<<2048, 256>>>();
        k_gcn<<<32768, 128>>>(bufs[it]);
        k_combine<<<dim3(32, 32), 256>>>(bufs[it + 1]);
    }

    // out = ((bc(x) + c1 + c2 + c3 + c4) @ Wo^T + b) / H
    k_gemmsum<<<dim3(1, 256), 256>>>(x, Wo_w, Wo_b, out, 0.25f);
}

// round 14
// speedup vs baseline: 2.3002x; 1.0392x over previous
#include <cuda_runtime.h>
#include <math.h>

// Problem dimensions (fixed by the dataset)
#define NN    32768      // total nodes B*NPG
#define BBg   8          // graphs
#define NPGc  4096       // nodes per graph
#define DINc  128
#define HHc   4
#define EEc   262144
#define CDIM  512        // H*DIN
#define BHc   32         // B*H

// ---------------- tf32 / cp.async helpers ----------------
__device__ __forceinline__ float tf32r(float x) {
    unsigned r;
    asm("cvt.rna.tf32.f32 %0, %1;" : "=r"(r) : "f"(x));
    return __uint_as_float(r);
}
__device__ __forceinline__ void mma8(float* c, const unsigned* a, const unsigned* b) {
    asm volatile(
        "mma.sync.aligned.m16n8k8.row.col.f32.tf32.tf32.f32 "
        "{%0,%1,%2,%3},{%4,%5,%6,%7},{%8,%9},{%0,%1,%2,%3};\n"
        : "+f"(c[0]), "+f"(c[1]), "+f"(c[2]), "+f"(c[3])
        : "r"(a[0]), "r"(a[1]), "r"(a[2]), "r"(a[3]), "r"(b[0]), "r"(b[1]));
}
__device__ __forceinline__ unsigned fbits(float x) { return __float_as_uint(x); }
__device__ __forceinline__ unsigned cvt_tf(float x) {
    unsigned r;
    asm("cvt.rna.tf32.f32 %0, %1;" : "=r"(r) : "f"(x));
    return r;
}
__device__ __forceinline__ unsigned smem_u32(const void* p) {
    unsigned r;
    asm("{.reg .u64 t; cvta.to.shared.u64 t, %1; cvt.u32.u64 %0, t;}" : "=r"(r) : "l"(p));
    return r;
}
__device__ __forceinline__ void cpa16(unsigned dst, const float* src) {
    asm volatile("cp.async.cg.shared.global [%0], [%1], 16;"
                 :: "r"(dst), "l"(__cvta_generic_to_global(src)));
}
#define CPCOMMIT() asm volatile("cp.async.commit_group;" ::: "memory")
#define CPWAIT1()  asm volatile("cp.async.wait_group 1;" ::: "memory")
#define CPWAIT0()  asm volatile("cp.async.wait_group 0;" ::: "memory")

// ---------------- scratch (device globals: allocation-free) ----------------
__device__ float g_q   [NN*CDIM];
__device__ float g_k   [NN*CDIM];
__device__ float g_c0  [NN*CDIM];   // cur_0 = broadcast(x)
__device__ float g_c1  [NN*CDIM];   // cur_1..cur_4 (kept for deferred acc)
__device__ float g_c2  [NN*CDIM];
__device__ float g_c3  [NN*CDIM];
__device__ float g_c4  [NN*CDIM];
__device__ float g_gcn [NN*CDIM];
__device__ float g_kvp [8*BHc*DINc*DINc]; // per-split partials
__device__ float g_kv  [BHc*DINc*DINc];
__device__ float g_vsum[BHc*DINc];
__device__ float g_ksum[BHc*DINc];
__device__ float g_den [NN*HHc];
__device__ int   g_deg   [NN];
__device__ float g_dis   [NN];
__device__ int   g_cursor[NN];
__device__ int   g_rowptr[NN];
__device__ int   g_incl  [NN];
__device__ int   g_bsum[128];
__device__ int   g_boff[128];
__device__ int   g_ecol[EEc];
__device__ float g_ew  [EEc];

// ---------------- init: cur0 = broadcast(x over heads) ----------------
__global__ void k_init(const float* __restrict__ x) {
    int i = blockIdx.x * blockDim.x + threadIdx.x;
    int n  = i >> 7;
    int r  = i & 127;
    int d4 = r & 31;
    float4 v = reinterpret_cast<const float4*>(x)[n * 32 + d4];
    reinterpret_cast<float4*>(g_c0)[i] = v;
}

__global__ void k_zero_pre() {
    int i = blockIdx.x * blockDim.x + threadIdx.x;
    if (i < NN) { g_deg[i] = 0; g_cursor[i] = 0; }
    if (i < BHc * DINc) g_ksum[i] = 0.f;
}

__global__ void k_count(const int* __restrict__ row) {
    int e = blockIdx.x * blockDim.x + threadIdx.x;
    if (e < EEc) atomicAdd(&g_deg[row[e]], 1);
}

__global__ void k_dis() {
    int n = blockIdx.x * blockDim.x + threadIdx.x;
    if (n < NN) {
        int d = g_deg[n];
        g_dis[n] = (d > 0) ? (1.0f / sqrtf((float)d)) : 0.0f;
    }
}

// ---------------- prefix scan over deg -> rowptr (exclusive) ----------------
__global__ void k_scanA() {
    __shared__ int s[256];
    int t = threadIdx.x;
    int i = blockIdx.x * 256 + t;
    int v = g_deg[i];
    s[t] = v; __syncthreads();
    for (int off = 1; off < 256; off <<= 1) {
        int u = (t >= off) ? s[t - off] : 0;
        __syncthreads();
        s[t] += u;
        __syncthreads();
    }
    g_incl[i] = s[t];
    if (t == 255) g_bsum[blockIdx.x] = s[255];
}

__global__ void k_scanB() {
    __shared__ int s[128];
    int t = threadIdx.x;
    int v = g_bsum[t];
    s[t] = v; __syncthreads();
    for (int off = 1; off < 128; off <<= 1) {
        int u = (t >= off) ? s[t - off] : 0;
        __syncthreads();
        s[t] += u;
        __syncthreads();
    }
    g_boff[t] = s[t] - v;
}

__global__ void k_scanC() {
    int i = blockIdx.x * blockDim.x + threadIdx.x;
    if (i < NN) g_rowptr[i] = g_incl[i] - g_deg[i] + g_boff[i >> 8];
}

__global__ void k_fill(const int* __restrict__ row, const int* __restrict__ col) {
    int e = blockIdx.x * blockDim.x + threadIdx.x;
    if (e < EEc) {
        int r = row[e], c = col[e];
        int pos = g_rowptr[r] + atomicAdd(&g_cursor[r], 1);
        g_ecol[pos] = c;
        g_ew[pos]   = g_dis[r] * g_dis[c];
    }
}

// ---------------- tf32 MMA GEMM, cp.async 2-stage: C = scale*(A@B^T + bias) ----------
// 128x128 tile, 8 warps, warp tile 64x32, K-chunk 32. Raw fp32 in smem, cvt in frags.
// Dynamic smem: 2 stages x (sA 4608 + sB 4608) floats = 73728 B.
__global__ void __launch_bounds__(256)
k_gemm(const float* __restrict__ A, const float* __restrict__ B,
       const float* __restrict__ bias, float* __restrict__ C,
       int M, int N, int K, float scale, int normalize) {
    extern __shared__ __align__(16) float sm[];
    const int STG = 9216;
    int t  = threadIdx.x;
    int bm = blockIdx.y * 128;
    int bn = blockIdx.x * 128;
    int wid = t >> 5, lane = t & 31, gid = lane >> 2, tig = lane & 3;
    int wm = (wid & 1) * 64, wn = (wid >> 1) * 32;
    unsigned sbu = smem_u32(sm);

    float c[4][4][4];
    #pragma unroll
    for (int i = 0; i < 4; i++)
        #pragma unroll
        for (int j = 0; j < 4; j++)
            #pragma unroll
            for (int r = 0; r < 4; r++) c[i][j][r] = 0.f;

    int nch = K >> 5;
    {   // prologue: chunk 0 -> stage 0
        unsigned sa = sbu, sb = sbu + 4608 * 4;
        #pragma unroll
        for (int l = 0; l < 4; l++) {
            int id = t + 256 * l, row = id >> 3, v = (id & 7) * 4;
            cpa16(sa + (row * 36 + v) * 4, &A[(bm + row) * K + v]);
            cpa16(sb + (row * 36 + v) * 4, &B[(bn + row) * K + v]);
        }
        CPCOMMIT();
    }
    for (int ci = 0; ci < nch; ci++) {
        int st = ci & 1;
        if (ci + 1 < nch) {
            int kc2 = (ci + 1) << 5;
            unsigned sa = sbu + (st ^ 1) * STG * 4, sb = sa + 4608 * 4;
            #pragma unroll
            for (int l = 0; l < 4; l++) {
                int id = t + 256 * l, row = id >> 3, v = (id & 7) * 4;
                cpa16(sa + (row * 36 + v) * 4, &A[(bm + row) * K + kc2 + v]);
                cpa16(sb + (row * 36 + v) * 4, &B[(bn + row) * K + kc2 + v]);
            }
            CPCOMMIT();
            CPWAIT1();
        } else {
            CPWAIT0();
        }
        __syncthreads();
        float* sAf = sm + st * STG;
        float* sBf = sAf + 4608;
        #pragma unroll
        for (int ks = 0; ks < 4; ks++) {
            int k0 = ks * 8;
            unsigned a[4][4], b[4][2];
            #pragma unroll
            for (int mt = 0; mt < 4; mt++) {
                int m = wm + 16 * mt + gid;
                a[mt][0] = cvt_tf(sAf[m * 36 + k0 + tig]);
                a[mt][1] = cvt_tf(sAf[(m + 8) * 36 + k0 + tig]);
                a[mt][2] = cvt_tf(sAf[m * 36 + k0 + tig + 4]);
                a[mt][3] = cvt_tf(sAf[(m + 8) * 36 + k0 + tig + 4]);
            }
            #pragma unroll
            for (int nt = 0; nt < 4; nt++) {
                int n = wn + 8 * nt + gid;
                b[nt][0] = cvt_tf(sBf[n * 36 + k0 + tig]);
                b[nt][1] = cvt_tf(sBf[n * 36 + k0 + tig + 4]);
            }
            #pragma unroll
            for (int mt = 0; mt < 4; mt++)
                #pragma unroll
                for (int nt = 0; nt < 4; nt++) mma8(c[mt][nt], a[mt], b[nt]);
        }
        __syncthreads();
    }

    // bias first (normalization is applied to xW + b)
    #pragma unroll
    for (int nt = 0; nt < 4; nt++) {
        float2 bb = *reinterpret_cast<const float2*>(&bias[bn + wn + 8 * nt + 2 * tig]);
        #pragma unroll
        for (int mt = 0; mt < 4; mt++) {
            c[mt][nt][0] += bb.x; c[mt][nt][1] += bb.y;
            c[mt][nt][2] += bb.x; c[mt][nt][3] += bb.y;
        }
    }

    if (normalize) {
        float* sred = sm;            // [row][4] partials
        float* sinv = sm + 512;      // [row]
        #pragma unroll
        for (int mt = 0; mt < 4; mt++) {
            #pragma unroll
            for (int half = 0; half < 2; half++) {
                float ss = 0.f;
                #pragma unroll
                for (int nt = 0; nt < 4; nt++) {
                    float v0 = c[mt][nt][half * 2 + 0];
                    float v1 = c[mt][nt][half * 2 + 1];
                    ss += v0 * v0 + v1 * v1;
                }
                ss += __shfl_xor_sync(0xffffffffu, ss, 1);
                ss += __shfl_xor_sync(0xffffffffu, ss, 2);
                if (tig == 0)
                    sred[(wm + 16 * mt + gid + 8 * half) * 4 + (wn >> 5)] = ss;
            }
        }
        __syncthreads();
        if (t < 128)
            sinv[t] = 1.0f / sqrtf(sred[t * 4] + sred[t * 4 + 1] +
                                   sred[t * 4 + 2] + sred[t * 4 + 3]);
        __syncthreads();
        #pragma unroll
        for (int mt = 0; mt < 4; mt++) {
            #pragma unroll
            for (int half = 0; half < 2; half++) {
                float iv = sinv[wm + 16 * mt + gid + 8 * half];
                #pragma unroll
                for (int nt = 0; nt < 4; nt++) {
                    c[mt][nt][half * 2 + 0] *= iv;
                    c[mt][nt][half * 2 + 1] *= iv;
                }
            }
        }
    }

    #pragma unroll
    for (int mt = 0; mt < 4; mt++) {
        int r0 = bm + wm + 16 * mt + gid;
        #pragma unroll
        for (int nt = 0; nt < 4; nt++) {
            int col = bn + wn + 8 * nt + 2 * tig;
            float2 o0, o1;
            o0.x = scale * c[mt][nt][0];
            o0.y = scale * c[mt][nt][1];
            o1.x = scale * c[mt][nt][2];
            o1.y = scale * c[mt][nt][3];
            *reinterpret_cast<float2*>(&C[r0 * N + col])       = o0;
            *reinterpret_cast<float2*>(&C[(r0 + 8) * N + col]) = o1;
        }
    }
}

// ---------------- final GEMM with deferred acc: A = bc(x) + c1 + c2 + c3 + c4 ----------
__global__ void __launch_bounds__(256)
k_gemmsum(const float* __restrict__ x, const float* __restrict__ B,
          const float* __restrict__ bias, float* __restrict__ C,
          float scale) {
    const int N = DINc, K = CDIM;
    __shared__ __align__(16) float sA[128 * 36];
    __shared__ __align__(16) float sB[128 * 36];
    int t  = threadIdx.x;
    int bm = blockIdx.y * 128;
    int wid = t >> 5, lane = t & 31, gid = lane >> 2, tig = lane & 3;
    int wm = (wid & 1) * 64, wn = (wid >> 1) * 32;

    float c[4][4][4];
    #pragma unroll
    for (int i = 0; i < 4; i++)
        #pragma unroll
        for (int j = 0; j < 4; j++)
            #pragma unroll
            for (int r = 0; r < 4; r++) c[i][j][r] = 0.f;

    for (int kc = 0; kc < K; kc += 32) {
        #pragma unroll
        for (int l = 0; l < 4; l++) {
            int id = t + 256 * l;
            int row = id >> 3;
            int c4  = (id & 7) * 4;
            int gr  = bm + row;
            int kk  = kc + c4;
            float4 v  = *reinterpret_cast<const float4*>(&x[gr * DINc + (kk & 127)]);
            float4 a1 = *reinterpret_cast<const float4*>(&g_c1[gr * CDIM + kk]);
            float4 a2 = *reinterpret_cast<const float4*>(&g_c2[gr * CDIM + kk]);
            float4 a3 = *reinterpret_cast<const float4*>(&g_c3[gr * CDIM + kk]);
            float4 a4 = *reinterpret_cast<const float4*>(&g_c4[gr * CDIM + kk]);
            v.x += a1.x + a2.x + a3.x + a4.x;
            v.y += a1.y + a2.y + a3.y + a4.y;
            v.z += a1.z + a2.z + a3.z + a4.z;
            v.w += a1.w + a2.w + a3.w + a4.w;
            sA[row * 36 + c4 + 0] = tf32r(v.x);
            sA[row * 36 + c4 + 1] = tf32r(v.y);
            sA[row * 36 + c4 + 2] = tf32r(v.z);
            sA[row * 36 + c4 + 3] = tf32r(v.w);
            float4 w = *reinterpret_cast<const float4*>(&B[row * K + kk]);
            sB[row * 36 + c4 + 0] = tf32r(w.x);
            sB[row * 36 + c4 + 1] = tf32r(w.y);
            sB[row * 36 + c4 + 2] = tf32r(w.z);
            sB[row * 36 + c4 + 3] = tf32r(w.w);
        }
        __syncthreads();
        #pragma unroll
        for (int ks = 0; ks < 4; ks++) {
            int k0 = ks * 8;
            unsigned a[4][4], b[4][2];
            #pragma unroll
            for (int mt = 0; mt < 4; mt++) {
                int m = wm + 16 * mt + gid;
                a[mt][0] = fbits(sA[m * 36 + k0 + tig]);
                a[mt][1] = fbits(sA[(m + 8) * 36 + k0 + tig]);
                a[mt][2] = fbits(sA[m * 36 + k0 + tig + 4]);
                a[mt][3] = fbits(sA[(m + 8) * 36 + k0 + tig + 4]);
            }
            #pragma unroll
            for (int nt = 0; nt < 4; nt++) {
                int n = wn + 8 * nt + gid;
                b[nt][0] = fbits(sB[n * 36 + k0 + tig]);
                b[nt][1] = fbits(sB[n * 36 + k0 + tig + 4]);
            }
            #pragma unroll
            for (int mt = 0; mt < 4; mt++)
                #pragma unroll
                for (int nt = 0; nt < 4; nt++) mma8(c[mt][nt], a[mt], b[nt]);
        }
        __syncthreads();
    }

    #pragma unroll
    for (int mt = 0; mt < 4; mt++) {
        int r0 = bm + wm + 16 * mt + gid;
        #pragma unroll
        for (int nt = 0; nt < 4; nt++) {
            int col = wn + 8 * nt + 2 * tig;
            float2 bb = *reinterpret_cast<const float2*>(&bias[col]);
            float2 o0, o1;
            o0.x = scale * (c[mt][nt][0] + bb.x);
            o0.y = scale * (c[mt][nt][1] + bb.y);
            o1.x = scale * (c[mt][nt][2] + bb.x);
            o1.y = scale * (c[mt][nt][3] + bb.y);
            *reinterpret_cast<float2*>(&C[r0 * N + col])       = o0;
            *reinterpret_cast<float2*>(&C[(r0 + 8) * N + col]) = o1;
        }
    }
}

// ---------------- ksum (once): column sums of normalized k per (b,h) ----------------
__global__ void k_colsum() {
    int bh = blockIdx.x;
    int b = bh >> 2, h = bh & 3;
    int nb = blockIdx.y * 128;
    int e = threadIdx.x;
    float s = 0.f;
    for (int n = 0; n < 128; n++)
        s += g_k[((b * NPGc + nb + n) * HHc + h) * DINc + e];
    atomicAdd(&g_ksum[bh * DINc + e], s);
}

// ---------------- den[n,h] = q . ksum + n_nodes (iteration-invariant) ----------------
__global__ void k_den(const int* __restrict__ n_nodes) {
    int gt   = blockIdx.x * blockDim.x + threadIdx.x;
    int w    = gt >> 5;
    int lane = threadIdx.x & 31;
    int n = w >> 2, h = w & 3;
    int b = n >> 12;
    float4 q = reinterpret_cast<float4*>(g_q)[w * 32 + lane];
    float4 s = reinterpret_cast<float4*>(g_ksum)[((b << 2) | h) * 32 + lane];
    float d = q.x * s.x + q.y * s.y + q.z * s.z + q.w * s.w;
    #pragma unroll
    for (int off = 16; off > 0; off >>= 1) d += __shfl_xor_sync(0xffffffffu, d, off);
    if (lane == 0) g_den[w] = d + (float)n_nodes[b];
}

__global__ void k_zero_vsum() {
    int i = blockIdx.x * blockDim.x + threadIdx.x;
    if (i < BHc * DINc) g_vsum[i] = 0.f;
}

// ---------------- kv partials + fused vsum, cp.async 2-stage ---------------------
// Natural-layout smem [node][dim] (raw fp32, pad 136); cvt in fragment phase.
// Dynamic smem: 2 stages x (sK 4352 + sV 4352) floats = 69632 B.
__global__ void __launch_bounds__(256) k_kv(const float* __restrict__ cur) {
    extern __shared__ __align__(16) float sm[];
    const int STG = 8704;
    int bh = blockIdx.x, sp = blockIdx.y;
    int b = bh >> 2, h = bh & 3;
    int t = threadIdx.x;
    int wid = t >> 5, lane = t & 31, gid = lane >> 2, tig = lane & 3;
    int wm = (wid & 1) * 64, wn = (wid >> 1) * 32;
    int r4 = t >> 5, d4 = t & 31;
    unsigned sbu = smem_u32(sm);

    float c[4][4][4];
    #pragma unroll
    for (int i = 0; i < 4; i++)
        #pragma unroll
        for (int j = 0; j < 4; j++)
            #pragma unroll
            for (int r = 0; r < 4; r++) c[i][j][r] = 0.f;
    float vs0 = 0.f, vs1 = 0.f, vs2 = 0.f, vs3 = 0.f;

    int nb0 = sp * 512;
    {   // prologue: chunk 0 -> stage 0
        unsigned sk = sbu, sv = sbu + 4352 * 4;
        #pragma unroll
        for (int l = 0; l < 4; l++) {
            int id = t + 256 * l, nl = id >> 5, v = (id & 31) * 4;
            int fidx = ((b * NPGc + nb0 + nl) * HHc + h) * DINc + v;
            cpa16(sk + (nl * 136 + v) * 4, &g_k[fidx]);
            cpa16(sv + (nl * 136 + v) * 4, &cur[fidx]);
        }
        CPCOMMIT();
    }
    for (int ci = 0; ci < 16; ci++) {
        int st = ci & 1;
        if (ci + 1 < 16) {
            int nb2 = nb0 + (ci + 1) * 32;
            unsigned sk = sbu + (st ^ 1) * STG * 4, sv = sk + 4352 * 4;
            #pragma unroll
            for (int l = 0; l < 4; l++) {
                int id = t + 256 * l, nl = id >> 5, v = (id & 31) * 4;
                int fidx = ((b * NPGc + nb2 + nl) * HHc + h) * DINc + v;
                cpa16(sk + (nl * 136 + v) * 4, &g_k[fidx]);
                cpa16(sv + (nl * 136 + v) * 4, &cur[fidx]);
            }
            CPCOMMIT();
            CPWAIT1();
        } else {
            CPWAIT0();
        }
        __syncthreads();
        float* sKf = sm + st * STG;
        float* sVf = sKf + 4352;
        {   // fused vsum from raw fp32 smem (identical values to pre-pipeline code)
            #pragma unroll
            for (int rr = 0; rr < 4; rr++) {
                float4 vv = *reinterpret_cast<const float4*>(&sVf[(r4 * 4 + rr) * 136 + 4 * d4]);
                vs0 += vv.x; vs1 += vv.y; vs2 += vv.z; vs3 += vv.w;
            }
        }
        #pragma unroll
        for (int ks = 0; ks < 4; ks++) {
            int k0 = ks * 8;
            unsigned a[4][4], bf[4][2];
            #pragma unroll
            for (int mt = 0; mt < 4; mt++) {
                int m = wm + 16 * mt + gid;
                a[mt][0] = cvt_tf(sKf[(k0 + tig) * 136 + m]);
                a[mt][1] = cvt_tf(sKf[(k0 + tig) * 136 + m + 8]);
                a[mt][2] = cvt_tf(sKf[(k0 + tig + 4) * 136 + m]);
                a[mt][3] = cvt_tf(sKf[(k0 + tig + 4) * 136 + m + 8]);
            }
            #pragma unroll
            for (int nt = 0; nt < 4; nt++) {
                int e = wn + 8 * nt + gid;
                bf[nt][0] = cvt_tf(sVf[(k0 + tig) * 136 + e]);
                bf[nt][1] = cvt_tf(sVf[(k0 + tig + 4) * 136 + e]);
            }
            #pragma unroll
            for (int mt = 0; mt < 4; mt++)
                #pragma unroll
                for (int nt = 0; nt < 4; nt++) mma8(c[mt][nt], a[mt], bf[nt]);
        }
        __syncthreads();
    }

    // vsum partials -> global (REDG); per-thread partial covers its (r4, d4) rows
    atomicAdd(&g_vsum[bh * DINc + 4 * d4 + 0], vs0);
    atomicAdd(&g_vsum[bh * DINc + 4 * d4 + 1], vs1);
    atomicAdd(&g_vsum[bh * DINc + 4 * d4 + 2], vs2);
    atomicAdd(&g_vsum[bh * DINc + 4 * d4 + 3], vs3);

    float* dst = &g_kvp[(sp * BHc + bh) * (DINc * DINc)];
    #pragma unroll
    for (int mt = 0; mt < 4; mt++) {
        int r0 = wm + 16 * mt + gid;
        #pragma unroll
        for (int nt = 0; nt < 4; nt++) {
            int col = wn + 8 * nt + 2 * tig;
            *reinterpret_cast<float2*>(&dst[r0 * 128 + col]) =
                make_float2(c[mt][nt][0], c[mt][nt][1]);
            *reinterpret_cast<float2*>(&dst[(r0 + 8) * 128 + col]) =
                make_float2(c[mt][nt][2], c[mt][nt][3]);
        }
    }
}

__global__ void k_kvreduce() {
    int i = blockIdx.x * 256 + threadIdx.x;
    float s = 0.f;
    #pragma unroll
    for (int sp = 0; sp < 8; sp++) s += g_kvp[sp * (BHc * DINc * DINc) + i];
    g_kv[i] = s;
}

// ---------------- GCN gather: gcn[n] = sum_{e in CSR row n} w[e] * cur[col[e]] ----------------
__global__ void k_gcn(const float* __restrict__ cur) {
    int n = blockIdx.x;
    int t = threadIdx.x;
    int s = g_rowptr[n];
    int e = s + g_deg[n];
    float4 acc = make_float4(0.f, 0.f, 0.f, 0.f);
    for (int i = s; i < e; i++) {
        int   c = g_ecol[i];
        float w = g_ew[i];
        float4 v = reinterpret_cast<const float4*>(cur)[c * 128 + t];
        acc.x += w * v.x; acc.y += w * v.y; acc.z += w * v.z; acc.w += w * v.w;
    }
    reinterpret_cast<float4*>(g_gcn)[n * 128 + t] = acc;
}

// ---------------- combine, cp.async 2-stage: attn = (q@kv + vsum)/den; curNew = .5*gcn + .5*attn
// Dynamic smem: 2 stages x (sQ 4608 + sKV 4352) floats = 71680 B.
__global__ void __launch_bounds__(256) k_combine(float* __restrict__ curNew) {
    extern __shared__ __align__(16) float sm[];
    const int STG = 8960;
    int bh = blockIdx.x, ch = blockIdx.y;
    int b = bh >> 2, h = bh & 3;
    int t = threadIdx.x;
    int wid = t >> 5, lane = t & 31, gid = lane >> 2, tig = lane & 3;
    int wm = (wid & 1) * 64, wn = (wid >> 1) * 32;
    int nbase = ch * 128;
    unsigned sbu = smem_u32(sm);
    const float* kvb = &g_kv[bh * (DINc * DINc)];

    float c[4][4][4];
    #pragma unroll
    for (int i = 0; i < 4; i++)
        #pragma unroll
        for (int j = 0; j < 4; j++)
            #pragma unroll
            for (int r = 0; r < 4; r++) c[i][j][r] = 0.f;

    {   // prologue: chunk 0 -> stage 0
        unsigned sq = sbu, skv = sbu + 4608 * 4;
        #pragma unroll
        for (int l = 0; l < 4; l++) {
            int id = t + 256 * l;
            int row = id >> 3, v = (id & 7) * 4;
            cpa16(sq + (row * 36 + v) * 4,
                  &g_q[((b * NPGc + nbase + row) * HHc + h) * DINc + v]);
            int drow = id >> 5, ve = (id & 31) * 4;
            cpa16(skv + (drow * 136 + ve) * 4, &kvb[drow * 128 + ve]);
        }
        CPCOMMIT();
    }
    for (int ci = 0; ci < 4; ci++) {
        int st = ci & 1;
        if (ci + 1 < 4) {
            int kc2 = (ci + 1) << 5;
            unsigned sq = sbu + (st ^ 1) * STG * 4, skv = sq + 4608 * 4;
            #pragma unroll
            for (int l = 0; l < 4; l++) {
                int id = t + 256 * l;
                int row = id >> 3, v = (id & 7) * 4;
                cpa16(sq + (row * 36 + v) * 4,
                      &g_q[((b * NPGc + nbase + row) * HHc + h) * DINc + kc2 + v]);
                int drow = id >> 5, ve = (id & 31) * 4;
                cpa16(skv + (drow * 136 + ve) * 4, &kvb[(kc2 + drow) * 128 + ve]);
            }
            CPCOMMIT();
            CPWAIT1();
        } else {
            CPWAIT0();
        }
        __syncthreads();
        float* sQf  = sm + st * STG;
        float* sKVf = sQf + 4608;
        #pragma unroll
        for (int ks = 0; ks < 4; ks++) {
            int k0 = ks * 8;
            unsigned a[4][4], bfr[4][2];
            #pragma unroll
            for (int mt = 0; mt < 4; mt++) {
                int m = wm + 16 * mt + gid;
                a[mt][0] = cvt_tf(sQf[m * 36 + k0 + tig]);
                a[mt][1] = cvt_tf(sQf[(m + 8) * 36 + k0 + tig]);
                a[mt][2] = cvt_tf(sQf[m * 36 + k0 + tig + 4]);
                a[mt][3] = cvt_tf(sQf[(m + 8) * 36 + k0 + tig + 4]);
            }
            #pragma unroll
            for (int nt = 0; nt < 4; nt++) {
                int e = wn + 8 * nt + gid;
                bfr[nt][0] = cvt_tf(sKVf[(k0 + tig) * 136 + e]);
                bfr[nt][1] = cvt_tf(sKVf[(k0 + tig + 4) * 136 + e]);
            }
            #pragma unroll
            for (int mt = 0; mt < 4; mt++)
                #pragma unroll
                for (int nt = 0; nt < 4; nt++) mma8(c[mt][nt], a[mt], bfr[nt]);
        }
        __syncthreads();
    }

    #pragma unroll
    for (int mt = 0; mt < 4; mt++) {
        int nl0 = nbase + wm + 16 * mt + gid;
        #pragma unroll
        for (int half = 0; half < 2; half++) {
            int nl = nl0 + half * 8;
            float inv = 1.0f / g_den[(b * NPGc + nl) * HHc + h];
            #pragma unroll
            for (int nt = 0; nt < 4; nt++) {
                int e = wn + 8 * nt + 2 * tig;
                int base = ((b * NPGc + nl) * HHc + h) * DINc + e;
                float cv0 = c[mt][nt][half * 2 + 0];
                float cv1 = c[mt][nt][half * 2 + 1];
                float2 vs = *reinterpret_cast<const float2*>(&g_vsum[bh * DINc + e]);
                float2 gc = *reinterpret_cast<const float2*>(&g_gcn[base]);
                float o0 = 0.5f * (gc.x + (cv0 + vs.x) * inv);
                float o1 = 0.5f * (gc.y + (cv1 + vs.y) * inv);
                *reinterpret_cast<float2*>(&curNew[base]) = make_float2(o0, o1);
            }
        }
    }
}

// ---------------- launcher ----------------
extern "C" void kernel_launch(void* const* d_in, const int* in_sizes, int n_in,
                              void* d_out, int out_size) {
    const float* x    = (const float*)d_in[0];
    const float* Wq_w = (const float*)d_in[1];
    const float* Wq_b = (const float*)d_in[2];
    const float* Wk_w = (const float*)d_in[3];
    const float* Wk_b = (const float*)d_in[4];
    const float* Wo_w = (const float*)d_in[5];
    const float* Wo_b = (const float*)d_in[6];
    const int*   edge = (const int*)d_in[7];
    const int*   nnod = (const int*)d_in[8];
    const int* row = edge;
    const int* col = edge + EEc;
    float* out = (float*)d_out;

    float *pq, *pk, *pc0, *pc1, *pc2, *pc3, *pc4;
    cudaGetSymbolAddress((void**)&pq,  g_q);
    cudaGetSymbolAddress((void**)&pk,  g_k);
    cudaGetSymbolAddress((void**)&pc0, g_c0);
    cudaGetSymbolAddress((void**)&pc1, g_c1);
    cudaGetSymbolAddress((void**)&pc2, g_c2);
    cudaGetSymbolAddress((void**)&pc3, g_c3);
    cudaGetSymbolAddress((void**)&pc4, g_c4);
    float* bufs[5] = {pc0, pc1, pc2, pc3, pc4};

    cudaFuncSetAttribute(k_gemm,    cudaFuncAttributeMaxDynamicSharedMemorySize, 73728);
    cudaFuncSetAttribute(k_kv,      cudaFuncAttributeMaxDynamicSharedMemorySize, 69632);
    cudaFuncSetAttribute(k_combine, cudaFuncAttributeMaxDynamicSharedMemorySize, 71680);

    // init + graph preprocessing (once per call)
    k_init<<<16384, 256>>>(x);
    k_zero_pre<<<128, 256>>>();
    k_count<<<1024, 256>>>(row);
    k_dis<<<128, 256>>>();
    k_scanA<<<128, 256>>>();
    k_scanB<<<1, 128>>>();
    k_scanC<<<128, 256>>>();
    k_fill<<<1024, 256>>>(row, col);

    // projections (normalize fused into epilogue) + invariant attention terms
    k_gemm<<<dim3(4, 256), 256, 73728>>>(x, Wq_w, Wq_b, pq, NN, CDIM, DINc, 1.0f, 1);
    k_gemm<<<dim3(4, 256), 256, 73728>>>(x, Wk_w, Wk_b, pk, NN, CDIM, DINc, 1.0f, 1);
    k_colsum<<<dim3(32, 32), 128>>>();             // ksum (k is iteration-invariant)
    k_den<<<16384, 256>>>(nnod);

    // K_ORDER = 4 propagation steps; cur_t kept in separate buffers (deferred acc)
    for (int it = 0; it < 4; it++) {
        k_zero_vsum<<<16, 256>>>();
        k_kv<<<dim3(32, 8), 256, 69632>>>(bufs[it]);   // kv partials + fused vsum
        k_kvreduce<<<2048, 256>>>();
        k_gcn<<<32768, 128>>>(bufs[it]);
        k_combine<<<dim3(32, 32), 256, 71680>>>(bufs[it + 1]);
    }

    // out = ((bc(x) + c1 + c2 + c3 + c4) @ Wo^T + b) / H
    k_gemmsum<<<dim3(1, 256), 256>>>(x, Wo_w, Wo_b, out, 0.25f);
}